// round 4
// baseline (speedup 1.0000x reference)
#include <cuda_runtime.h>
#include <cstdint>
#include <cstddef>

// Problem constants
// B=1024, K=50 classes, C=8 centers, H=512
// inputs: d_in[0]=x[1024,512], d_in[1]=class_mu[50,8,512], d_in[2]=mask[8,512], d_in[3]=W[512,512]
// output: concat(mul[1024,8,512], k_assign[1024,50,8], distances[1024,50,8]) fp32

__device__ float g_munorm[400];  // ||class_mu[k,c]||^2

__device__ __forceinline__ unsigned long long ffma2(unsigned long long a,
                                                    unsigned long long b,
                                                    unsigned long long c) {
    unsigned long long d;
    asm("fma.rn.f32x2 %0, %1, %2, %3;" : "=l"(d) : "l"(a), "l"(b), "l"(c));
    return d;
}

// ---------------------------------------------------------------------------
// GEMM: out[r,d] = sum_h x[r>>3,h] * mask[r&7,h] * W[h,d]
// M=8192, N=512, Kdim=512. Tiles 128x128x8, 256 threads, 8x8 microtile,
// accumulators held as packed f32x2 pairs (fma.rn.f32x2).
// ---------------------------------------------------------------------------
__global__ void __launch_bounds__(256)
gemm_masked_kernel(const float* __restrict__ x, const float* __restrict__ mask,
                   const float* __restrict__ W, float* __restrict__ out) {
    __shared__ float2 As[8][128];                    // duplicated (v,v) pairs
    __shared__ __align__(16) float Bs[8][128];

    const int tid = threadIdx.x;
    const int bm = blockIdx.y << 7;
    const int bn = blockIdx.x << 7;

    // A tile loaders: 128 rows x 8 k, one float4 per thread
    const int arow = tid >> 1;
    const int akq  = (tid & 1) << 2;
    const int grow = bm + arow;
    const float* xptr = x    + ((size_t)(grow >> 3) << 9) + akq;
    const float* mptr = mask + ((size_t)(grow & 7)  << 9) + akq;

    // B tile loaders: 8 k-rows x 128 cols
    const int brow = tid >> 5;
    const int bcol = (tid & 31) << 2;
    const float* wptr = W + ((size_t)brow << 9) + bn + bcol;

    const int ty = tid >> 4;   // 0..15
    const int tx = tid & 15;   // 0..15

    unsigned long long acc[8][4];
#pragma unroll
    for (int i = 0; i < 8; i++)
#pragma unroll
        for (int j = 0; j < 4; j++) acc[i][j] = 0ULL;

    for (int k0 = 0; k0 < 512; k0 += 8) {
        float4 xa = *(const float4*)(xptr + k0);
        float4 ma = *(const float4*)(mptr + k0);
        float v0 = xa.x * ma.x, v1 = xa.y * ma.y, v2 = xa.z * ma.z, v3 = xa.w * ma.w;
        As[akq + 0][arow] = make_float2(v0, v0);
        As[akq + 1][arow] = make_float2(v1, v1);
        As[akq + 2][arow] = make_float2(v2, v2);
        As[akq + 3][arow] = make_float2(v3, v3);
        *(float4*)&Bs[brow][bcol] = *(const float4*)(wptr + ((size_t)k0 << 9));
        __syncthreads();

#pragma unroll
        for (int kk = 0; kk < 8; kk++) {
            unsigned long long a[8];
#pragma unroll
            for (int i = 0; i < 8; i++)
                a[i] = *reinterpret_cast<const unsigned long long*>(&As[kk][(ty << 3) + i]);
            ulonglong2 b01 = *reinterpret_cast<const ulonglong2*>(&Bs[kk][tx << 3]);
            ulonglong2 b23 = *reinterpret_cast<const ulonglong2*>(&Bs[kk][(tx << 3) + 4]);
            unsigned long long b[4] = {b01.x, b01.y, b23.x, b23.y};
#pragma unroll
            for (int i = 0; i < 8; i++)
#pragma unroll
                for (int j = 0; j < 4; j++)
                    acc[i][j] = ffma2(a[i], b[j], acc[i][j]);
        }
        __syncthreads();
    }

#pragma unroll
    for (int i = 0; i < 8; i++) {
        int row = bm + (ty << 3) + i;
        float* optr = out + (size_t)row * 512 + bn + (tx << 3);
        float2 p0 = *(float2*)&acc[i][0];
        float2 p1 = *(float2*)&acc[i][1];
        float2 p2 = *(float2*)&acc[i][2];
        float2 p3 = *(float2*)&acc[i][3];
        *(float4*)(optr)     = make_float4(p0.x, p0.y, p1.x, p1.y);
        *(float4*)(optr + 4) = make_float4(p2.x, p2.y, p3.x, p3.y);
    }
}

// ---------------------------------------------------------------------------
// ||class_mu[k,c]||^2 for all 400 (k,c) rows. One warp per row.
// Launch <<<50, 256>>>.
// ---------------------------------------------------------------------------
__global__ void munorm_kernel(const float* __restrict__ class_mu) {
    const int warp = threadIdx.x >> 5;
    const int lane = threadIdx.x & 31;
    const int r = blockIdx.x * 8 + warp;  // 0..399
    const float4* row = (const float4*)(class_mu + (size_t)r * 512);
    float s = 0.f;
#pragma unroll
    for (int j = lane; j < 128; j += 32) {
        float4 v = row[j];
        s += v.x * v.x + v.y * v.y + v.z * v.z + v.w * v.w;
    }
#pragma unroll
    for (int o = 16; o; o >>= 1) s += __shfl_down_sync(0xffffffffu, s, o);
    if (lane == 0) g_munorm[r] = s;
}

// ---------------------------------------------------------------------------
// Fused scoring: per block, 8 batch rows (BB=8).
//   cnorm[bb,c]   = ||mul[b,c]||^2          (from smem copy)
//   dot[bb,k,c]   = mul[b,c,:] . mu[k,c,:]  (4 k's per inner pass)
//   score         = 1/(1 + cnorm - 2 dot + munorm)
//   distances     = score / (sum_c score + eps)
//   k_assign      = distances / sum_c distances
// Launch <<<128, 256, 144128>>>.
// ---------------------------------------------------------------------------
__global__ void __launch_bounds__(256)
fused_score_kernel(const float* __restrict__ mul, const float* __restrict__ class_mu,
                   float* __restrict__ out_ka, float* __restrict__ out_dist) {
    extern __shared__ float sm[];
    float* s_mul   = sm;              // 8*8*512 = 32768 floats
    float* s_cnorm = sm + 32768;      // 64 floats
    float* s_dots  = sm + 32832;      // 8*50*8 = 3200 floats

    const int tid  = threadIdx.x;
    const int lane = tid & 31;
    const int warp = tid >> 5;        // 0..7
    const int b0   = blockIdx.x << 3; // first batch row of this block

    // Stage mul[b0:b0+8, :, :] into smem (contiguous 128 KB chunk)
    {
        const float4* src = (const float4*)(mul + (size_t)b0 * 8 * 512);
        float4* dst = (float4*)s_mul;
        for (int i = tid; i < 8192; i += 256) dst[i] = src[i];
    }
    __syncthreads();

    // cnorm: 64 rows, warp per row
    for (int r = warp; r < 64; r += 8) {
        const float4* row = (const float4*)s_mul + r * 128;
        float s = 0.f;
#pragma unroll
        for (int j = lane; j < 128; j += 32) {
            float4 v = row[j];
            s += v.x * v.x + v.y * v.y + v.z * v.z + v.w * v.w;
        }
#pragma unroll
        for (int o = 16; o; o >>= 1) s += __shfl_down_sync(0xffffffffu, s, o);
        if (lane == 0) s_cnorm[r] = s;
    }
    __syncthreads();

    // dots: q enumerates (k-quad, c): 13 quads x 8 c = 104 tasks, 13 per warp.
    const float4* s_mul4 = (const float4*)s_mul;
    for (int q = warp; q < 104; q += 8) {
        const int c  = q & 7;
        const int k0 = (q >> 3) << 2;
        const float4* mu0 = (const float4*)(class_mu + ((size_t)((k0 + 0) * 8 + c)) * 512);
        const float4* mu1 = (const float4*)(class_mu + ((size_t)((k0 + 1) * 8 + c)) * 512);
        const float4* mu2 = (const float4*)(class_mu + ((size_t)((k0 + 2) * 8 + c)) * 512);
        const float4* mu3 = (const float4*)(class_mu + ((size_t)((k0 + 3) * 8 + c)) * 512);
        const bool v1 = (k0 + 1) < 50, v2 = (k0 + 2) < 50, v3 = (k0 + 3) < 50;

        float acc[4][8];
#pragma unroll
        for (int kk = 0; kk < 4; kk++)
#pragma unroll
            for (int bb = 0; bb < 8; bb++) acc[kk][bb] = 0.f;

#pragma unroll
        for (int j = lane; j < 128; j += 32) {
            float4 a0 = mu0[j];
            float4 a1 = v1 ? mu1[j] : make_float4(0.f, 0.f, 0.f, 0.f);
            float4 a2 = v2 ? mu2[j] : make_float4(0.f, 0.f, 0.f, 0.f);
            float4 a3 = v3 ? mu3[j] : make_float4(0.f, 0.f, 0.f, 0.f);
#pragma unroll
            for (int bb = 0; bb < 8; bb++) {
                float4 v = s_mul4[((bb << 3) + c) * 128 + j];
                acc[0][bb] += v.x * a0.x + v.y * a0.y + v.z * a0.z + v.w * a0.w;
                acc[1][bb] += v.x * a1.x + v.y * a1.y + v.z * a1.z + v.w * a1.w;
                acc[2][bb] += v.x * a2.x + v.y * a2.y + v.z * a2.z + v.w * a2.w;
                acc[3][bb] += v.x * a3.x + v.y * a3.y + v.z * a3.z + v.w * a3.w;
            }
        }
#pragma unroll
        for (int kk = 0; kk < 4; kk++) {
            const int k = k0 + kk;
#pragma unroll
            for (int bb = 0; bb < 8; bb++) {
                float s = acc[kk][bb];
#pragma unroll
                for (int o = 16; o; o >>= 1) s += __shfl_down_sync(0xffffffffu, s, o);
                if (lane == 0 && k < 50) s_dots[(bb * 50 + k) * 8 + c] = s;
            }
        }
    }
    __syncthreads();

    // finalize: 400 (bb,k) pairs
    for (int p = tid; p < 400; p += 256) {
        const int bb = p / 50;
        const int k  = p % 50;
        float sc[8];
        float S = 0.f;
#pragma unroll
        for (int c = 0; c < 8; c++) {
            float d2 = 1.f + s_cnorm[(bb << 3) + c] - 2.f * s_dots[(p << 3) + c]
                     + g_munorm[(k << 3) + c];
            float v = 1.f / d2;
            sc[c] = v;
            S += v;
        }
        const float inv1 = 1.f / (S + 1e-8f);
        float dist[8];
        float T = 0.f;
#pragma unroll
        for (int c = 0; c < 8; c++) { dist[c] = sc[c] * inv1; T += dist[c]; }
        const float inv2 = 1.f / T;
        const size_t base = ((size_t)(b0 + bb) * 50 + k) << 3;
#pragma unroll
        for (int c = 0; c < 8; c++) {
            out_dist[base + c] = dist[c];
            out_ka[base + c]   = dist[c] * inv2;
        }
    }
}

extern "C" void kernel_launch(void* const* d_in, const int* in_sizes, int n_in,
                              void* d_out, int out_size) {
    const float* x        = (const float*)d_in[0];
    const float* class_mu = (const float*)d_in[1];
    const float* mask     = (const float*)d_in[2];
    const float* W        = (const float*)d_in[3];

    float* out      = (float*)d_out;
    float* out_mul  = out;                                  // 1024*8*512
    float* out_ka   = out + (size_t)1024 * 8 * 512;         // 1024*50*8
    float* out_dist = out_ka + (size_t)1024 * 50 * 8;       // 1024*50*8

    const size_t fused_smem = (32768 + 64 + 3200) * sizeof(float);  // 144128 B
    cudaFuncSetAttribute(fused_score_kernel,
                         cudaFuncAttributeMaxDynamicSharedMemorySize,
                         (int)fused_smem);

    munorm_kernel<<<50, 256>>>(class_mu);
    gemm_masked_kernel<<<dim3(4, 64), 256>>>(x, mask, W, out_mul);
    fused_score_kernel<<<128, 256, fused_smem>>>(out_mul, class_mu, out_ka, out_dist);
}

// round 6
// speedup vs baseline: 1.8147x; 1.8147x over previous
#include <cuda_runtime.h>
#include <cuda_bf16.h>
#include <cstdint>
#include <cstddef>

// B=1024, K=50 classes, C=8 centers, H=512
// inputs: d_in[0]=x[1024,512], d_in[1]=class_mu[50,8,512], d_in[2]=mask[8,512], d_in[3]=W[512,512]
// output: concat(mul[1024,8,512] fp32, k_assign[1024,50,8], distances[1024,50,8])

// ---------------------------------------------------------------------------
// Scratch (__device__ globals — allocation-free)
// ---------------------------------------------------------------------------
__device__ float g_munorm[400];
// A split: [8192 rows, 1024 cols] bf16: cols [0,512)=hi(masked x), [512,1024)=lo
__device__ __align__(16) __nv_bfloat16 g_Asplit[8192 * 1024];
// W split (transposed, K-major): [512 n, 1024 k] bf16: cols [0,512)=hi, [512,1024)=lo
__device__ __align__(16) __nv_bfloat16 g_Wsplit[512 * 1024];

// ---------------------------------------------------------------------------
// Baseline-target PTX helpers (no sm_103a-only features!)
// ---------------------------------------------------------------------------
__device__ __forceinline__ uint32_t smem_u32(const void* p) {
    uint32_t a;
    asm("{ .reg .u64 t; cvta.to.shared.u64 t, %1; cvt.u32.u64 %0, t; }"
        : "=r"(a) : "l"(p));
    return a;
}

__device__ __forceinline__ void ldsm_x4(uint32_t& r0, uint32_t& r1, uint32_t& r2,
                                        uint32_t& r3, uint32_t addr) {
    asm volatile("ldmatrix.sync.aligned.m8n8.x4.shared.b16 {%0,%1,%2,%3}, [%4];"
                 : "=r"(r0), "=r"(r1), "=r"(r2), "=r"(r3) : "r"(addr));
}

__device__ __forceinline__ void ldsm_x2(uint32_t& r0, uint32_t& r1, uint32_t addr) {
    asm volatile("ldmatrix.sync.aligned.m8n8.x2.shared.b16 {%0,%1}, [%2];"
                 : "=r"(r0), "=r"(r1) : "r"(addr));
}

__device__ __forceinline__ void mma16816(float* c, uint32_t a0, uint32_t a1,
                                         uint32_t a2, uint32_t a3,
                                         uint32_t b0, uint32_t b1) {
    asm volatile(
        "mma.sync.aligned.m16n8k16.row.col.f32.bf16.bf16.f32 "
        "{%0,%1,%2,%3}, {%4,%5,%6,%7}, {%8,%9}, {%0,%1,%2,%3};"
        : "+f"(c[0]), "+f"(c[1]), "+f"(c[2]), "+f"(c[3])
        : "r"(a0), "r"(a1), "r"(a2), "r"(a3), "r"(b0), "r"(b1));
}

#define CP_ASYNC16(dst, src) \
    asm volatile("cp.async.cg.shared.global [%0], [%1], 16;" \
                 :: "r"(dst), "l"(src) : "memory")
#define CP_COMMIT() asm volatile("cp.async.commit_group;" ::: "memory")

// ---------------------------------------------------------------------------
// Split A: g_Asplit[r, 0:512]=bf16(x*mask), [512:1024]=bf16 residual.
// <<<4096, 256>>>
// ---------------------------------------------------------------------------
__global__ void split_a_kernel(const float* __restrict__ x,
                               const float* __restrict__ mask) {
    const int idx = blockIdx.x * 256 + threadIdx.x;  // 0 .. 1048575
    const int r = idx >> 7;          // 0..8191
    const int h = (idx & 127) << 2;  // 0..508
    const float4 xv = *(const float4*)(x + ((size_t)(r >> 3) << 9) + h);
    const float4 mv = *(const float4*)(mask + ((size_t)(r & 7) << 9) + h);
    float v[4] = {xv.x * mv.x, xv.y * mv.y, xv.z * mv.z, xv.w * mv.w};
    __nv_bfloat16 hi[4], lo[4];
#pragma unroll
    for (int i = 0; i < 4; i++) {
        hi[i] = __float2bfloat16(v[i]);
        lo[i] = __float2bfloat16(v[i] - __bfloat162float(hi[i]));
    }
    __nv_bfloat162* hp = (__nv_bfloat162*)(g_Asplit + (size_t)r * 1024 + h);
    __nv_bfloat162* lp = (__nv_bfloat162*)(g_Asplit + (size_t)r * 1024 + 512 + h);
    hp[0] = __halves2bfloat162(hi[0], hi[1]);
    hp[1] = __halves2bfloat162(hi[2], hi[3]);
    lp[0] = __halves2bfloat162(lo[0], lo[1]);
    lp[1] = __halves2bfloat162(lo[2], lo[3]);
}

// ---------------------------------------------------------------------------
// Transpose + split W. <<<dim3(16,16), dim3(32,8)>>>
// ---------------------------------------------------------------------------
__global__ void transpose_w_kernel(const float* __restrict__ W) {
    __shared__ float tile[32][33];
    const int tx = threadIdx.x, ty = threadIdx.y;
    const int kt = blockIdx.x * 32, nt = blockIdx.y * 32;
#pragma unroll
    for (int i = 0; i < 32; i += 8)
        tile[ty + i][tx] = W[(size_t)(kt + ty + i) * 512 + nt + tx];
    __syncthreads();
#pragma unroll
    for (int i = 0; i < 32; i += 8) {
        const int n = nt + ty + i;
        const int k = kt + tx;
        const float v = tile[tx][ty + i];
        const __nv_bfloat16 hi = __float2bfloat16(v);
        const __nv_bfloat16 lo = __float2bfloat16(v - __bfloat162float(hi));
        g_Wsplit[(size_t)n * 1024 + k] = hi;
        g_Wsplit[(size_t)n * 1024 + 512 + k] = lo;
    }
}

// ---------------------------------------------------------------------------
// ||class_mu[k,c]||^2. <<<50, 256>>>
// ---------------------------------------------------------------------------
__global__ void munorm_kernel(const float* __restrict__ class_mu) {
    const int warp = threadIdx.x >> 5;
    const int lane = threadIdx.x & 31;
    const int r = blockIdx.x * 8 + warp;
    const float4* row = (const float4*)(class_mu + (size_t)r * 512);
    float s = 0.f;
#pragma unroll
    for (int j = lane; j < 128; j += 32) {
        float4 v = row[j];
        s += v.x * v.x + v.y * v.y + v.z * v.z + v.w * v.w;
    }
#pragma unroll
    for (int o = 16; o; o >>= 1) s += __shfl_down_sync(0xffffffffu, s, o);
    if (lane == 0) g_munorm[r] = s;
}

// ---------------------------------------------------------------------------
// HMMA GEMM (mma.sync bf16): out[8192,512] over virtual K=1536
// passes: A[hi]*B[hi] + A[hi]*B[lo] + A[lo]*B[hi]
// CTA tile 128x128, warp tile 64x32, K-chunk 32, cp.async double buffer.
// SMEM row stride 80B -> conflict-free ldmatrix without swizzle.
// <<<dim3(4,64), 256>>>
// ---------------------------------------------------------------------------
#define SM_STRIDE 80
#define BUF_BYTES 20480  // (128 rows A + 128 rows B) * 80B

__global__ void __launch_bounds__(256, 2)
mma_gemm_kernel(float* __restrict__ out) {
    __shared__ __align__(16) char smem[2 * BUF_BYTES];
    const uint32_t smem_base = smem_u32(smem);

    const int tid = threadIdx.x;
    const int lane = tid & 31;
    const int wid = tid >> 5;
    const int wm = wid >> 2;  // 0..1
    const int wn = wid & 3;   // 0..3
    const int bn = blockIdx.x;  // 0..3
    const int bm = blockIdx.y;  // 0..63

    const __nv_bfloat16* Abase = g_Asplit + (size_t)bm * 128 * 1024;
    const __nv_bfloat16* Bbase = g_Wsplit + (size_t)bn * 128 * 1024;

    // cp.async: 512 x 16B for A, 512 x 16B for B; 2+2 per thread
    const int lrow = tid >> 2;       // 0..63 (+64 on second pass)
    const int lseg = tid & 3;        // 0..3

    auto issue = [&](int c, int stage) {
        const int p = c >> 4, sub = c & 15;
        const int acol = ((p == 2) ? 512 : 0) + sub * 32;  // A: hi,hi,lo
        const int bcol = ((p == 1) ? 512 : 0) + sub * 32;  // B: hi,lo,hi
        const uint32_t sA = smem_base + stage * BUF_BYTES;
        const uint32_t sB = sA + 128 * SM_STRIDE;
#pragma unroll
        for (int t = 0; t < 2; t++) {
            const int row = lrow + t * 64;
            CP_ASYNC16(sA + row * SM_STRIDE + lseg * 16,
                       Abase + (size_t)row * 1024 + acol + lseg * 8);
        }
#pragma unroll
        for (int t = 0; t < 2; t++) {
            const int row = lrow + t * 64;
            CP_ASYNC16(sB + row * SM_STRIDE + lseg * 16,
                       Bbase + (size_t)row * 1024 + bcol + lseg * 8);
        }
    };

    float acc[4][4][4];
#pragma unroll
    for (int i = 0; i < 4; i++)
#pragma unroll
        for (int j = 0; j < 4; j++)
#pragma unroll
            for (int q = 0; q < 4; q++) acc[i][j][q] = 0.f;

    issue(0, 0);
    CP_COMMIT();

    for (int c = 0; c < 48; c++) {
        const int stage = c & 1;
        if (c + 1 < 48) {
            issue(c + 1, stage ^ 1);
            CP_COMMIT();
            asm volatile("cp.async.wait_group 1;" ::: "memory");
        } else {
            asm volatile("cp.async.wait_group 0;" ::: "memory");
        }
        __syncthreads();

        const uint32_t sA = smem_base + stage * BUF_BYTES;
        const uint32_t sB = sA + 128 * SM_STRIDE;
#pragma unroll
        for (int ks = 0; ks < 2; ks++) {
            uint32_t a[4][4];
#pragma unroll
            for (int mf = 0; mf < 4; mf++) {
                const int row = wm * 64 + mf * 16 + (lane & 15);
                const uint32_t col = ks * 32 + ((lane >> 4) << 4);
                ldsm_x4(a[mf][0], a[mf][1], a[mf][2], a[mf][3],
                        sA + row * SM_STRIDE + col);
            }
            uint32_t b[4][2];
#pragma unroll
            for (int nf = 0; nf < 4; nf++) {
                const int row = wn * 32 + nf * 8 + (lane & 7);
                const uint32_t col = ks * 32 + (((lane >> 3) & 1) << 4);
                ldsm_x2(b[nf][0], b[nf][1], sB + row * SM_STRIDE + col);
            }
#pragma unroll
            for (int mf = 0; mf < 4; mf++)
#pragma unroll
                for (int nf = 0; nf < 4; nf++)
                    mma16816(acc[mf][nf], a[mf][0], a[mf][1], a[mf][2], a[mf][3],
                             b[nf][0], b[nf][1]);
        }
        __syncthreads();
    }

    // Epilogue: fragment -> gmem float2 stores
    const int r0 = lane >> 2;          // 0..7
    const int c0 = (lane & 3) << 1;    // 0,2,4,6
#pragma unroll
    for (int mf = 0; mf < 4; mf++) {
        const int m = bm * 128 + wm * 64 + mf * 16 + r0;
#pragma unroll
        for (int nf = 0; nf < 4; nf++) {
            const int n = bn * 128 + wn * 32 + nf * 8 + c0;
            *(float2*)(out + (size_t)m * 512 + n) =
                make_float2(acc[mf][nf][0], acc[mf][nf][1]);
            *(float2*)(out + (size_t)(m + 8) * 512 + n) =
                make_float2(acc[mf][nf][2], acc[mf][nf][3]);
        }
    }
}

// ---------------------------------------------------------------------------
// Fused scoring (unchanged from R4 passing kernel). <<<128, 256, 144128>>>
// ---------------------------------------------------------------------------
__global__ void __launch_bounds__(256)
fused_score_kernel(const float* __restrict__ mul, const float* __restrict__ class_mu,
                   float* __restrict__ out_ka, float* __restrict__ out_dist) {
    extern __shared__ float sm[];
    float* s_mul   = sm;              // 8*8*512 = 32768 floats
    float* s_cnorm = sm + 32768;      // 64
    float* s_dots  = sm + 32832;      // 3200

    const int tid  = threadIdx.x;
    const int lane = tid & 31;
    const int warp = tid >> 5;
    const int b0   = blockIdx.x << 3;

    {
        const float4* src = (const float4*)(mul + (size_t)b0 * 8 * 512);
        float4* dst = (float4*)s_mul;
        for (int i = tid; i < 8192; i += 256) dst[i] = src[i];
    }
    __syncthreads();

    for (int r = warp; r < 64; r += 8) {
        const float4* row = (const float4*)s_mul + r * 128;
        float s = 0.f;
#pragma unroll
        for (int j = lane; j < 128; j += 32) {
            float4 v = row[j];
            s += v.x * v.x + v.y * v.y + v.z * v.z + v.w * v.w;
        }
#pragma unroll
        for (int o = 16; o; o >>= 1) s += __shfl_down_sync(0xffffffffu, s, o);
        if (lane == 0) s_cnorm[r] = s;
    }
    __syncthreads();

    const float4* s_mul4 = (const float4*)s_mul;
    for (int q = warp; q < 104; q += 8) {
        const int c  = q & 7;
        const int k0 = (q >> 3) << 2;
        const float4* mu0 = (const float4*)(class_mu + ((size_t)((k0 + 0) * 8 + c)) * 512);
        const float4* mu1 = (const float4*)(class_mu + ((size_t)((k0 + 1) * 8 + c)) * 512);
        const float4* mu2 = (const float4*)(class_mu + ((size_t)((k0 + 2) * 8 + c)) * 512);
        const float4* mu3 = (const float4*)(class_mu + ((size_t)((k0 + 3) * 8 + c)) * 512);
        const bool v1 = (k0 + 1) < 50, v2 = (k0 + 2) < 50, v3 = (k0 + 3) < 50;

        float acc[4][8];
#pragma unroll
        for (int kk = 0; kk < 4; kk++)
#pragma unroll
            for (int bb = 0; bb < 8; bb++) acc[kk][bb] = 0.f;

#pragma unroll
        for (int j = lane; j < 128; j += 32) {
            float4 a0 = mu0[j];
            float4 a1 = v1 ? mu1[j] : make_float4(0.f, 0.f, 0.f, 0.f);
            float4 a2 = v2 ? mu2[j] : make_float4(0.f, 0.f, 0.f, 0.f);
            float4 a3 = v3 ? mu3[j] : make_float4(0.f, 0.f, 0.f, 0.f);
#pragma unroll
            for (int bb = 0; bb < 8; bb++) {
                float4 v = s_mul4[((bb << 3) + c) * 128 + j];
                acc[0][bb] += v.x * a0.x + v.y * a0.y + v.z * a0.z + v.w * a0.w;
                acc[1][bb] += v.x * a1.x + v.y * a1.y + v.z * a1.z + v.w * a1.w;
                acc[2][bb] += v.x * a2.x + v.y * a2.y + v.z * a2.z + v.w * a2.w;
                acc[3][bb] += v.x * a3.x + v.y * a3.y + v.z * a3.z + v.w * a3.w;
            }
        }
#pragma unroll
        for (int kk = 0; kk < 4; kk++) {
            const int k = k0 + kk;
#pragma unroll
            for (int bb = 0; bb < 8; bb++) {
                float s = acc[kk][bb];
#pragma unroll
                for (int o = 16; o; o >>= 1) s += __shfl_down_sync(0xffffffffu, s, o);
                if (lane == 0 && k < 50) s_dots[(bb * 50 + k) * 8 + c] = s;
            }
        }
    }
    __syncthreads();

    for (int p = tid; p < 400; p += 256) {
        const int bb = p / 50;
        const int k  = p % 50;
        float sc[8];
        float S = 0.f;
#pragma unroll
        for (int c = 0; c < 8; c++) {
            float d2 = 1.f + s_cnorm[(bb << 3) + c] - 2.f * s_dots[(p << 3) + c]
                     + g_munorm[(k << 3) + c];
            float v = 1.f / d2;
            sc[c] = v;
            S += v;
        }
        const float inv1 = 1.f / (S + 1e-8f);
        float dist[8];
        float T = 0.f;
#pragma unroll
        for (int c = 0; c < 8; c++) { dist[c] = sc[c] * inv1; T += dist[c]; }
        const float inv2 = 1.f / T;
        const size_t base = ((size_t)(b0 + bb) * 50 + k) << 3;
#pragma unroll
        for (int c = 0; c < 8; c++) {
            out_dist[base + c] = dist[c];
            out_ka[base + c]   = dist[c] * inv2;
        }
    }
}

// ---------------------------------------------------------------------------
extern "C" void kernel_launch(void* const* d_in, const int* in_sizes, int n_in,
                              void* d_out, int out_size) {
    const float* x        = (const float*)d_in[0];
    const float* class_mu = (const float*)d_in[1];
    const float* mask     = (const float*)d_in[2];
    const float* W        = (const float*)d_in[3];

    float* out      = (float*)d_out;
    float* out_mul  = out;                                  // 1024*8*512
    float* out_ka   = out + (size_t)1024 * 8 * 512;         // 1024*50*8
    float* out_dist = out_ka + (size_t)1024 * 50 * 8;       // 1024*50*8

    const size_t fused_smem = (32768 + 64 + 3200) * sizeof(float);  // 144128 B
    cudaFuncSetAttribute(fused_score_kernel,
                         cudaFuncAttributeMaxDynamicSharedMemorySize, (int)fused_smem);

    split_a_kernel<<<4096, 256>>>(x, mask);
    transpose_w_kernel<<<dim3(16, 16), dim3(32, 8)>>>(W);
    munorm_kernel<<<50, 256>>>(class_mu);
    mma_gemm_kernel<<<dim3(4, 64), 256>>>(out_mul);
    fused_score_kernel<<<128, 256, fused_smem>>>(out_mul, class_mu, out_ka, out_dist);
}

// round 7
// speedup vs baseline: 2.0196x; 1.1129x over previous
#include <cuda_runtime.h>
#include <cuda_bf16.h>
#include <cstdint>
#include <cstddef>

// B=1024, K=50 classes, C=8 centers, H=512
// inputs: d_in[0]=x[1024,512], d_in[1]=class_mu[50,8,512], d_in[2]=mask[8,512], d_in[3]=W[512,512]
// output: concat(mul[1024,8,512] fp32, k_assign[1024,50,8], distances[1024,50,8])

// ---------------------------------------------------------------------------
// Scratch (__device__ globals — allocation-free)
// ---------------------------------------------------------------------------
__device__ float g_munorm[400];
// A split: [8192 rows, 1024 cols] bf16: cols [0,512)=hi(masked x), [512,1024)=lo
__device__ __align__(16) __nv_bfloat16 g_Asplit[8192 * 1024];
// W split (transposed, K-major): [512 n, 1024 k] bf16: cols [0,512)=hi, [512,1024)=lo
__device__ __align__(16) __nv_bfloat16 g_Wsplit[512 * 1024];

// ---------------------------------------------------------------------------
// PTX helpers (baseline sm_103 target — no 'a'-suffix features)
// ---------------------------------------------------------------------------
__device__ __forceinline__ uint32_t smem_u32(const void* p) {
    uint32_t a;
    asm("{ .reg .u64 t; cvta.to.shared.u64 t, %1; cvt.u32.u64 %0, t; }"
        : "=r"(a) : "l"(p));
    return a;
}

__device__ __forceinline__ void ldsm_x4(uint32_t& r0, uint32_t& r1, uint32_t& r2,
                                        uint32_t& r3, uint32_t addr) {
    asm volatile("ldmatrix.sync.aligned.m8n8.x4.shared.b16 {%0,%1,%2,%3}, [%4];"
                 : "=r"(r0), "=r"(r1), "=r"(r2), "=r"(r3) : "r"(addr));
}

__device__ __forceinline__ void ldsm_x2(uint32_t& r0, uint32_t& r1, uint32_t addr) {
    asm volatile("ldmatrix.sync.aligned.m8n8.x2.shared.b16 {%0,%1}, [%2];"
                 : "=r"(r0), "=r"(r1) : "r"(addr));
}

__device__ __forceinline__ void mma16816(float* c, uint32_t a0, uint32_t a1,
                                         uint32_t a2, uint32_t a3,
                                         uint32_t b0, uint32_t b1) {
    asm volatile(
        "mma.sync.aligned.m16n8k16.row.col.f32.bf16.bf16.f32 "
        "{%0,%1,%2,%3}, {%4,%5,%6,%7}, {%8,%9}, {%0,%1,%2,%3};"
        : "+f"(c[0]), "+f"(c[1]), "+f"(c[2]), "+f"(c[3])
        : "r"(a0), "r"(a1), "r"(a2), "r"(a3), "r"(b0), "r"(b1));
}

#define CP_ASYNC16(dst, src) \
    asm volatile("cp.async.cg.shared.global [%0], [%1], 16;" \
                 :: "r"(dst), "l"(src) : "memory")
#define CP_COMMIT() asm volatile("cp.async.commit_group;" ::: "memory")

// Packed dual-fp32 FMA (compiled & validated on this toolchain in R4)
__device__ __forceinline__ unsigned long long ffma2(unsigned long long a,
                                                    unsigned long long b,
                                                    unsigned long long c) {
    unsigned long long d;
    asm("fma.rn.f32x2 %0, %1, %2, %3;" : "=l"(d) : "l"(a), "l"(b), "l"(c));
    return d;
}
__device__ __forceinline__ unsigned long long pack2(float lo, float hi) {
    unsigned long long p;
    asm("mov.b64 %0, {%1, %2};" : "=l"(p) : "f"(lo), "f"(hi));
    return p;
}
__device__ __forceinline__ float2 unpack2(unsigned long long p) {
    float2 f;
    asm("mov.b64 {%0, %1}, %2;" : "=f"(f.x), "=f"(f.y) : "l"(p));
    return f;
}

// ---------------------------------------------------------------------------
// Combined prep kernel: split A | transpose+split W | munorm.
// <<<4096 + 256 + 50 = 4402, 256>>>
// ---------------------------------------------------------------------------
__global__ void prep_kernel(const float* __restrict__ x,
                            const float* __restrict__ mask,
                            const float* __restrict__ W,
                            const float* __restrict__ class_mu) {
    __shared__ float tile[32][33];
    const int tid = threadIdx.x;
    const int blk = blockIdx.x;

    if (blk < 4096) {
        // ---- split A ----
        const int idx = blk * 256 + tid;         // 0 .. 1048575
        const int r = idx >> 7;                  // 0..8191
        const int h = (idx & 127) << 2;          // 0..508
        const float4 xv = *(const float4*)(x + ((size_t)(r >> 3) << 9) + h);
        const float4 mv = *(const float4*)(mask + ((size_t)(r & 7) << 9) + h);
        float v[4] = {xv.x * mv.x, xv.y * mv.y, xv.z * mv.z, xv.w * mv.w};
        __nv_bfloat16 hi[4], lo[4];
#pragma unroll
        for (int i = 0; i < 4; i++) {
            hi[i] = __float2bfloat16(v[i]);
            lo[i] = __float2bfloat16(v[i] - __bfloat162float(hi[i]));
        }
        __nv_bfloat162* hp = (__nv_bfloat162*)(g_Asplit + (size_t)r * 1024 + h);
        __nv_bfloat162* lp = (__nv_bfloat162*)(g_Asplit + (size_t)r * 1024 + 512 + h);
        hp[0] = __halves2bfloat162(hi[0], hi[1]);
        hp[1] = __halves2bfloat162(hi[2], hi[3]);
        lp[0] = __halves2bfloat162(lo[0], lo[1]);
        lp[1] = __halves2bfloat162(lo[2], lo[3]);
    } else if (blk < 4096 + 256) {
        // ---- transpose + split W ----
        const int t = blk - 4096;
        const int kt = (t & 15) * 32, nt = (t >> 4) * 32;
        const int tx = tid & 31, ty = tid >> 5;  // ty 0..7
#pragma unroll
        for (int i = 0; i < 32; i += 8)
            tile[ty + i][tx] = W[(size_t)(kt + ty + i) * 512 + nt + tx];
        __syncthreads();
#pragma unroll
        for (int i = 0; i < 32; i += 8) {
            const int n = nt + ty + i;
            const int k = kt + tx;
            const float v = tile[tx][ty + i];
            const __nv_bfloat16 hi = __float2bfloat16(v);
            const __nv_bfloat16 lo = __float2bfloat16(v - __bfloat162float(hi));
            g_Wsplit[(size_t)n * 1024 + k] = hi;
            g_Wsplit[(size_t)n * 1024 + 512 + k] = lo;
        }
    } else {
        // ---- munorm ----
        const int warp = tid >> 5;
        const int lane = tid & 31;
        const int r = (blk - 4352) * 8 + warp;   // 0..399
        const float4* row = (const float4*)(class_mu + (size_t)r * 512);
        float s = 0.f;
#pragma unroll
        for (int j = lane; j < 128; j += 32) {
            float4 v = row[j];
            s += v.x * v.x + v.y * v.y + v.z * v.z + v.w * v.w;
        }
#pragma unroll
        for (int o = 16; o; o >>= 1) s += __shfl_down_sync(0xffffffffu, s, o);
        if (lane == 0) g_munorm[r] = s;
    }
}

// ---------------------------------------------------------------------------
// HMMA GEMM: out[8192,512] over virtual K=1536
// (passes: A[hi]*B[hi] + A[hi]*B[lo] + A[lo]*B[hi])
// CTA tile 128x128, warp tile 64x32, K-chunk 32.
// 4-stage cp.async pipeline, ONE __syncthreads per chunk.
// <<<dim3(4,64), 256, 81920>>>
// ---------------------------------------------------------------------------
#define SM_STRIDE 80
#define BUF_BYTES 20480  // (128 rows A + 128 rows B) * 80B

__global__ void __launch_bounds__(256, 2)
mma_gemm_kernel(float* __restrict__ out) {
    extern __shared__ __align__(16) char smem[];  // 4 * BUF_BYTES
    const uint32_t smem_base = smem_u32(smem);

    const int tid = threadIdx.x;
    const int lane = tid & 31;
    const int wid = tid >> 5;
    const int wm = wid >> 2;    // 0..1
    const int wn = wid & 3;     // 0..3
    const int bn = blockIdx.x;  // 0..3
    const int bm = blockIdx.y;  // 0..63

    const __nv_bfloat16* Abase = g_Asplit + (size_t)bm * 128 * 1024;
    const __nv_bfloat16* Bbase = g_Wsplit + (size_t)bn * 128 * 1024;

    const int lrow = tid >> 2;  // 0..63 (+64 second half)
    const int lseg = tid & 3;   // 0..3

    auto issue = [&](int c) {
        const int stage = c & 3;
        const int p = c >> 4, sub = c & 15;
        const int acol = ((p == 2) ? 512 : 0) + sub * 32;  // A: hi,hi,lo
        const int bcol = ((p == 1) ? 512 : 0) + sub * 32;  // B: hi,lo,hi
        const uint32_t sA = smem_base + stage * BUF_BYTES;
        const uint32_t sB = sA + 128 * SM_STRIDE;
#pragma unroll
        for (int t = 0; t < 2; t++) {
            const int row = lrow + t * 64;
            CP_ASYNC16(sA + row * SM_STRIDE + lseg * 16,
                       Abase + (size_t)row * 1024 + acol + lseg * 8);
        }
#pragma unroll
        for (int t = 0; t < 2; t++) {
            const int row = lrow + t * 64;
            CP_ASYNC16(sB + row * SM_STRIDE + lseg * 16,
                       Bbase + (size_t)row * 1024 + bcol + lseg * 8);
        }
        CP_COMMIT();
    };

    float acc[4][4][4];
#pragma unroll
    for (int i = 0; i < 4; i++)
#pragma unroll
        for (int j = 0; j < 4; j++)
#pragma unroll
            for (int q = 0; q < 4; q++) acc[i][j][q] = 0.f;

    issue(0);
    issue(1);
    issue(2);

    for (int c = 0; c < 48; c++) {
        // wait until stage c's copies are complete (per-thread), then barrier
        if (c <= 45)       asm volatile("cp.async.wait_group 2;" ::: "memory");
        else if (c == 46)  asm volatile("cp.async.wait_group 1;" ::: "memory");
        else               asm volatile("cp.async.wait_group 0;" ::: "memory");
        __syncthreads();
        // buffer (c+3)&3 == (c-1)&3: its readers finished compute(c-1) before
        // this barrier, so refilling it now is safe and overlaps compute(c).
        if (c + 3 < 48) issue(c + 3);

        const uint32_t sA = smem_base + (c & 3) * BUF_BYTES;
        const uint32_t sB = sA + 128 * SM_STRIDE;
#pragma unroll
        for (int ks = 0; ks < 2; ks++) {
            uint32_t a[4][4];
#pragma unroll
            for (int mf = 0; mf < 4; mf++) {
                const int row = wm * 64 + mf * 16 + (lane & 15);
                const uint32_t col = ks * 32 + ((lane >> 4) << 4);
                ldsm_x4(a[mf][0], a[mf][1], a[mf][2], a[mf][3],
                        sA + row * SM_STRIDE + col);
            }
            uint32_t b[4][2];
#pragma unroll
            for (int nf = 0; nf < 4; nf++) {
                const int row = wn * 32 + nf * 8 + (lane & 7);
                const uint32_t col = ks * 32 + (((lane >> 3) & 1) << 4);
                ldsm_x2(b[nf][0], b[nf][1], sB + row * SM_STRIDE + col);
            }
#pragma unroll
            for (int mf = 0; mf < 4; mf++)
#pragma unroll
                for (int nf = 0; nf < 4; nf++)
                    mma16816(acc[mf][nf], a[mf][0], a[mf][1], a[mf][2], a[mf][3],
                             b[nf][0], b[nf][1]);
        }
    }

    // Epilogue: fragment -> gmem float2 stores
    const int r0 = lane >> 2;          // 0..7
    const int c0 = (lane & 3) << 1;    // 0,2,4,6
#pragma unroll
    for (int mf = 0; mf < 4; mf++) {
        const int m = bm * 128 + wm * 64 + mf * 16 + r0;
#pragma unroll
        for (int nf = 0; nf < 4; nf++) {
            const int n = bn * 128 + wn * 32 + nf * 8 + c0;
            *(float2*)(out + (size_t)m * 512 + n) =
                make_float2(acc[mf][nf][0], acc[mf][nf][1]);
            *(float2*)(out + (size_t)(m + 8) * 512 + n) =
                make_float2(acc[mf][nf][2], acc[mf][nf][3]);
        }
    }
}

// ---------------------------------------------------------------------------
// Fused scoring, dot core converted to packed f32x2 FMAs.
// <<<128, 256, 144128>>>
// ---------------------------------------------------------------------------
__global__ void __launch_bounds__(256)
fused_score_kernel(const float* __restrict__ mul, const float* __restrict__ class_mu,
                   float* __restrict__ out_ka, float* __restrict__ out_dist) {
    extern __shared__ float sm[];
    float* s_mul   = sm;              // 8*8*512 = 32768 floats
    float* s_cnorm = sm + 32768;      // 64
    float* s_dots  = sm + 32832;      // 3200

    const int tid  = threadIdx.x;
    const int lane = tid & 31;
    const int warp = tid >> 5;
    const int b0   = blockIdx.x << 3;

    {
        const float4* src = (const float4*)(mul + (size_t)b0 * 8 * 512);
        float4* dst = (float4*)s_mul;
        for (int i = tid; i < 8192; i += 256) dst[i] = src[i];
    }
    __syncthreads();

    for (int r = warp; r < 64; r += 8) {
        const float4* row = (const float4*)s_mul + r * 128;
        float s = 0.f;
#pragma unroll
        for (int j = lane; j < 128; j += 32) {
            float4 v = row[j];
            s += v.x * v.x + v.y * v.y + v.z * v.z + v.w * v.w;
        }
#pragma unroll
        for (int o = 16; o; o >>= 1) s += __shfl_down_sync(0xffffffffu, s, o);
        if (lane == 0) s_cnorm[r] = s;
    }
    __syncthreads();

    const float4* s_mul4 = (const float4*)s_mul;
    for (int q = warp; q < 104; q += 8) {
        const int c  = q & 7;
        const int k0 = (q >> 3) << 2;
        const float4* mu0 = (const float4*)(class_mu + ((size_t)((k0 + 0) * 8 + c)) * 512);
        const float4* mu1 = (const float4*)(class_mu + ((size_t)((k0 + 1) * 8 + c)) * 512);
        const float4* mu2 = (const float4*)(class_mu + ((size_t)((k0 + 2) * 8 + c)) * 512);
        const float4* mu3 = (const float4*)(class_mu + ((size_t)((k0 + 3) * 8 + c)) * 512);
        const bool v1 = (k0 + 1) < 50, v2 = (k0 + 2) < 50, v3 = (k0 + 3) < 50;

        unsigned long long acc2[4][8];
#pragma unroll
        for (int kk = 0; kk < 4; kk++)
#pragma unroll
            for (int bb = 0; bb < 8; bb++) acc2[kk][bb] = 0ULL;

#pragma unroll
        for (int j = lane; j < 128; j += 32) {
            float4 a0 = mu0[j];
            float4 a1 = v1 ? mu1[j] : make_float4(0.f, 0.f, 0.f, 0.f);
            float4 a2 = v2 ? mu2[j] : make_float4(0.f, 0.f, 0.f, 0.f);
            float4 a3 = v3 ? mu3[j] : make_float4(0.f, 0.f, 0.f, 0.f);
            unsigned long long A[4][2] = {
                {pack2(a0.x, a0.y), pack2(a0.z, a0.w)},
                {pack2(a1.x, a1.y), pack2(a1.z, a1.w)},
                {pack2(a2.x, a2.y), pack2(a2.z, a2.w)},
                {pack2(a3.x, a3.y), pack2(a3.z, a3.w)}};
#pragma unroll
            for (int bb = 0; bb < 8; bb++) {
                float4 v = s_mul4[((bb << 3) + c) * 128 + j];
                unsigned long long v01 = pack2(v.x, v.y);
                unsigned long long v23 = pack2(v.z, v.w);
#pragma unroll
                for (int kk = 0; kk < 4; kk++) {
                    acc2[kk][bb] = ffma2(v01, A[kk][0], acc2[kk][bb]);
                    acc2[kk][bb] = ffma2(v23, A[kk][1], acc2[kk][bb]);
                }
            }
        }
#pragma unroll
        for (int kk = 0; kk < 4; kk++) {
            const int k = k0 + kk;
#pragma unroll
            for (int bb = 0; bb < 8; bb++) {
                float2 f = unpack2(acc2[kk][bb]);
                float s = f.x + f.y;
#pragma unroll
                for (int o = 16; o; o >>= 1) s += __shfl_down_sync(0xffffffffu, s, o);
                if (lane == 0 && k < 50) s_dots[(bb * 50 + k) * 8 + c] = s;
            }
        }
    }
    __syncthreads();

    for (int p = tid; p < 400; p += 256) {
        const int bb = p / 50;
        const int k  = p % 50;
        float sc[8];
        float S = 0.f;
#pragma unroll
        for (int c = 0; c < 8; c++) {
            float d2 = 1.f + s_cnorm[(bb << 3) + c] - 2.f * s_dots[(p << 3) + c]
                     + g_munorm[(k << 3) + c];
            float v = 1.f / d2;
            sc[c] = v;
            S += v;
        }
        const float inv1 = 1.f / (S + 1e-8f);
        float dist[8];
        float T = 0.f;
#pragma unroll
        for (int c = 0; c < 8; c++) { dist[c] = sc[c] * inv1; T += dist[c]; }
        const float inv2 = 1.f / T;
        const size_t base = ((size_t)(b0 + bb) * 50 + k) << 3;
#pragma unroll
        for (int c = 0; c < 8; c++) {
            out_dist[base + c] = dist[c];
            out_ka[base + c]   = dist[c] * inv2;
        }
    }
}

// ---------------------------------------------------------------------------
extern "C" void kernel_launch(void* const* d_in, const int* in_sizes, int n_in,
                              void* d_out, int out_size) {
    const float* x        = (const float*)d_in[0];
    const float* class_mu = (const float*)d_in[1];
    const float* mask     = (const float*)d_in[2];
    const float* W        = (const float*)d_in[3];

    float* out      = (float*)d_out;
    float* out_mul  = out;                                  // 1024*8*512
    float* out_ka   = out + (size_t)1024 * 8 * 512;         // 1024*50*8
    float* out_dist = out_ka + (size_t)1024 * 50 * 8;       // 1024*50*8

    const size_t gemm_smem  = 4 * BUF_BYTES;                         // 81920 B
    const size_t fused_smem = (32768 + 64 + 3200) * sizeof(float);   // 144128 B
    cudaFuncSetAttribute(mma_gemm_kernel,
                         cudaFuncAttributeMaxDynamicSharedMemorySize, (int)gemm_smem);
    cudaFuncSetAttribute(fused_score_kernel,
                         cudaFuncAttributeMaxDynamicSharedMemorySize, (int)fused_smem);

    prep_kernel<<<4096 + 256 + 50, 256>>>(x, mask, W, class_mu);
    mma_gemm_kernel<<<dim3(4, 64), 256, gemm_smem>>>(out_mul);
    fused_score_kernel<<<128, 256, fused_smem>>>(out_mul, class_mu, out_ka, out_dist);
}

// round 8
// speedup vs baseline: 2.6967x; 1.3353x over previous
#include <cuda_runtime.h>
#include <cuda_bf16.h>
#include <cstdint>
#include <cstddef>

// B=1024, K=50 classes, C=8 centers, H=512
// inputs: d_in[0]=x[1024,512], d_in[1]=class_mu[50,8,512], d_in[2]=mask[8,512], d_in[3]=W[512,512]
// output: concat(mul[1024,8,512] fp32, k_assign[1024,50,8], distances[1024,50,8])

// ---------------------------------------------------------------------------
// Scratch (__device__ globals — allocation-free)
// ---------------------------------------------------------------------------
__device__ float g_munorm[400];
// A split: [8192 rows, 1024 cols] bf16: cols [0,512)=hi(masked x), [512,1024)=lo
__device__ __align__(16) __nv_bfloat16 g_Asplit[8192 * 1024];
// W split (transposed, K-major): [512 n, 1024 k] bf16: cols [0,512)=hi, [512,1024)=lo
__device__ __align__(16) __nv_bfloat16 g_Wsplit[512 * 1024];
// bf16 copy of mul, c-major: [c][b][h]  (8 x 1024 x 512)
__device__ __align__(16) __nv_bfloat16 g_mulbf16[8 * 1024 * 512];
// bf16 padded class_mu, c-major: [c][k64][h] (8 x 64 x 512), zeros for k>=50
__device__ __align__(16) __nv_bfloat16 g_mubf16[8 * 64 * 512];
// dot products: [c][b][k64] fp32
__device__ __align__(16) float g_dot[8 * 1024 * 64];

// ---------------------------------------------------------------------------
// PTX helpers (baseline sm_103 target — no 'a'-suffix features)
// ---------------------------------------------------------------------------
__device__ __forceinline__ uint32_t smem_u32(const void* p) {
    uint32_t a;
    asm("{ .reg .u64 t; cvta.to.shared.u64 t, %1; cvt.u32.u64 %0, t; }"
        : "=r"(a) : "l"(p));
    return a;
}

__device__ __forceinline__ void ldsm_x4(uint32_t& r0, uint32_t& r1, uint32_t& r2,
                                        uint32_t& r3, uint32_t addr) {
    asm volatile("ldmatrix.sync.aligned.m8n8.x4.shared.b16 {%0,%1,%2,%3}, [%4];"
                 : "=r"(r0), "=r"(r1), "=r"(r2), "=r"(r3) : "r"(addr));
}

__device__ __forceinline__ void ldsm_x2(uint32_t& r0, uint32_t& r1, uint32_t addr) {
    asm volatile("ldmatrix.sync.aligned.m8n8.x2.shared.b16 {%0,%1}, [%2];"
                 : "=r"(r0), "=r"(r1) : "r"(addr));
}

__device__ __forceinline__ void mma16816(float* c, uint32_t a0, uint32_t a1,
                                         uint32_t a2, uint32_t a3,
                                         uint32_t b0, uint32_t b1) {
    asm volatile(
        "mma.sync.aligned.m16n8k16.row.col.f32.bf16.bf16.f32 "
        "{%0,%1,%2,%3}, {%4,%5,%6,%7}, {%8,%9}, {%0,%1,%2,%3};"
        : "+f"(c[0]), "+f"(c[1]), "+f"(c[2]), "+f"(c[3])
        : "r"(a0), "r"(a1), "r"(a2), "r"(a3), "r"(b0), "r"(b1));
}

#define CP_ASYNC16(dst, src) \
    asm volatile("cp.async.cg.shared.global [%0], [%1], 16;" \
                 :: "r"(dst), "l"(src) : "memory")
#define CP_COMMIT() asm volatile("cp.async.commit_group;" ::: "memory")

// ---------------------------------------------------------------------------
// Prep: split A | transpose+split W | munorm | class_mu -> padded bf16
// <<<4096 + 256 + 50 + 256 = 4658, 256>>>
// ---------------------------------------------------------------------------
__global__ void prep_kernel(const float* __restrict__ x,
                            const float* __restrict__ mask,
                            const float* __restrict__ W,
                            const float* __restrict__ class_mu) {
    __shared__ float tile[32][33];
    const int tid = threadIdx.x;
    const int blk = blockIdx.x;

    if (blk < 4096) {
        // ---- split A ----
        const int idx = blk * 256 + tid;         // 0 .. 1048575
        const int r = idx >> 7;                  // 0..8191
        const int h = (idx & 127) << 2;          // 0..508
        const float4 xv = *(const float4*)(x + ((size_t)(r >> 3) << 9) + h);
        const float4 mv = *(const float4*)(mask + ((size_t)(r & 7) << 9) + h);
        float v[4] = {xv.x * mv.x, xv.y * mv.y, xv.z * mv.z, xv.w * mv.w};
        __nv_bfloat16 hi[4], lo[4];
#pragma unroll
        for (int i = 0; i < 4; i++) {
            hi[i] = __float2bfloat16(v[i]);
            lo[i] = __float2bfloat16(v[i] - __bfloat162float(hi[i]));
        }
        __nv_bfloat162* hp = (__nv_bfloat162*)(g_Asplit + (size_t)r * 1024 + h);
        __nv_bfloat162* lp = (__nv_bfloat162*)(g_Asplit + (size_t)r * 1024 + 512 + h);
        hp[0] = __halves2bfloat162(hi[0], hi[1]);
        hp[1] = __halves2bfloat162(hi[2], hi[3]);
        lp[0] = __halves2bfloat162(lo[0], lo[1]);
        lp[1] = __halves2bfloat162(lo[2], lo[3]);
    } else if (blk < 4096 + 256) {
        // ---- transpose + split W ----
        const int t = blk - 4096;
        const int kt = (t & 15) * 32, nt = (t >> 4) * 32;
        const int tx = tid & 31, ty = tid >> 5;  // ty 0..7
#pragma unroll
        for (int i = 0; i < 32; i += 8)
            tile[ty + i][tx] = W[(size_t)(kt + ty + i) * 512 + nt + tx];
        __syncthreads();
#pragma unroll
        for (int i = 0; i < 32; i += 8) {
            const int n = nt + ty + i;
            const int k = kt + tx;
            const float v = tile[tx][ty + i];
            const __nv_bfloat16 hi = __float2bfloat16(v);
            const __nv_bfloat16 lo = __float2bfloat16(v - __bfloat162float(hi));
            g_Wsplit[(size_t)n * 1024 + k] = hi;
            g_Wsplit[(size_t)n * 1024 + 512 + k] = lo;
        }
    } else if (blk < 4096 + 256 + 50) {
        // ---- munorm ----
        const int warp = tid >> 5;
        const int lane = tid & 31;
        const int r = (blk - 4352) * 8 + warp;   // 0..399
        const float4* row = (const float4*)(class_mu + (size_t)r * 512);
        float s = 0.f;
#pragma unroll
        for (int j = lane; j < 128; j += 32) {
            float4 v = row[j];
            s += v.x * v.x + v.y * v.y + v.z * v.z + v.w * v.w;
        }
#pragma unroll
        for (int o = 16; o; o >>= 1) s += __shfl_down_sync(0xffffffffu, s, o);
        if (lane == 0) g_munorm[r] = s;
    } else {
        // ---- class_mu -> g_mubf16[c][k64][h], zero padded ----
        const int t = blk - 4402;
        const int idx4 = t * 256 + tid;          // 0 .. 65535 (x4 elems)
        const int row = idx4 >> 7;               // 0..511 = c*64+k
        const int h = (idx4 & 127) << 2;
        const int c = row >> 6, k = row & 63;
        float4 v = make_float4(0.f, 0.f, 0.f, 0.f);
        if (k < 50) v = *(const float4*)(class_mu + (((size_t)k * 8 + c) << 9) + h);
        __nv_bfloat162* dst = (__nv_bfloat162*)(g_mubf16 + (size_t)row * 512 + h);
        dst[0] = __halves2bfloat162(__float2bfloat16(v.x), __float2bfloat16(v.y));
        dst[1] = __halves2bfloat162(__float2bfloat16(v.z), __float2bfloat16(v.w));
    }
}

// ---------------------------------------------------------------------------
// HMMA GEMM: out[8192,512] over virtual K=1536
// (passes: A[hi]*B[hi] + A[hi]*B[lo] + A[lo]*B[hi])
// CTA tile 128x128, warp tile 64x32, K-chunk 32.
// 4-stage cp.async pipeline, ONE __syncthreads per chunk.
// Epilogue also emits bf16(mul) to g_mulbf16[c][b][h].
// <<<dim3(4,64), 256, 81920>>>
// ---------------------------------------------------------------------------
#define SM_STRIDE 80
#define BUF_BYTES 20480  // (128 rows A + 128 rows B) * 80B

__global__ void __launch_bounds__(256, 2)
mma_gemm_kernel(float* __restrict__ out) {
    extern __shared__ __align__(16) char smem[];  // 4 * BUF_BYTES
    const uint32_t smem_base = smem_u32(smem);

    const int tid = threadIdx.x;
    const int lane = tid & 31;
    const int wid = tid >> 5;
    const int wm = wid >> 2;    // 0..1
    const int wn = wid & 3;     // 0..3
    const int bn = blockIdx.x;  // 0..3
    const int bm = blockIdx.y;  // 0..63

    const __nv_bfloat16* Abase = g_Asplit + (size_t)bm * 128 * 1024;
    const __nv_bfloat16* Bbase = g_Wsplit + (size_t)bn * 128 * 1024;

    const int lrow = tid >> 2;  // 0..63 (+64 second half)
    const int lseg = tid & 3;   // 0..3

    auto issue = [&](int c) {
        const int stage = c & 3;
        const int p = c >> 4, sub = c & 15;
        const int acol = ((p == 2) ? 512 : 0) + sub * 32;  // A: hi,hi,lo
        const int bcol = ((p == 1) ? 512 : 0) + sub * 32;  // B: hi,lo,hi
        const uint32_t sA = smem_base + stage * BUF_BYTES;
        const uint32_t sB = sA + 128 * SM_STRIDE;
#pragma unroll
        for (int t = 0; t < 2; t++) {
            const int row = lrow + t * 64;
            CP_ASYNC16(sA + row * SM_STRIDE + lseg * 16,
                       Abase + (size_t)row * 1024 + acol + lseg * 8);
        }
#pragma unroll
        for (int t = 0; t < 2; t++) {
            const int row = lrow + t * 64;
            CP_ASYNC16(sB + row * SM_STRIDE + lseg * 16,
                       Bbase + (size_t)row * 1024 + bcol + lseg * 8);
        }
        CP_COMMIT();
    };

    float acc[4][4][4];
#pragma unroll
    for (int i = 0; i < 4; i++)
#pragma unroll
        for (int j = 0; j < 4; j++)
#pragma unroll
            for (int q = 0; q < 4; q++) acc[i][j][q] = 0.f;

    issue(0);
    issue(1);
    issue(2);

    for (int c = 0; c < 48; c++) {
        if (c <= 45)       asm volatile("cp.async.wait_group 2;" ::: "memory");
        else if (c == 46)  asm volatile("cp.async.wait_group 1;" ::: "memory");
        else               asm volatile("cp.async.wait_group 0;" ::: "memory");
        __syncthreads();
        if (c + 3 < 48) issue(c + 3);

        const uint32_t sA = smem_base + (c & 3) * BUF_BYTES;
        const uint32_t sB = sA + 128 * SM_STRIDE;
#pragma unroll
        for (int ks = 0; ks < 2; ks++) {
            uint32_t a[4][4];
#pragma unroll
            for (int mf = 0; mf < 4; mf++) {
                const int row = wm * 64 + mf * 16 + (lane & 15);
                const uint32_t col = ks * 32 + ((lane >> 4) << 4);
                ldsm_x4(a[mf][0], a[mf][1], a[mf][2], a[mf][3],
                        sA + row * SM_STRIDE + col);
            }
            uint32_t b[4][2];
#pragma unroll
            for (int nf = 0; nf < 4; nf++) {
                const int row = wn * 32 + nf * 8 + (lane & 7);
                const uint32_t col = ks * 32 + (((lane >> 3) & 1) << 4);
                ldsm_x2(b[nf][0], b[nf][1], sB + row * SM_STRIDE + col);
            }
#pragma unroll
            for (int mf = 0; mf < 4; mf++)
#pragma unroll
                for (int nf = 0; nf < 4; nf++)
                    mma16816(acc[mf][nf], a[mf][0], a[mf][1], a[mf][2], a[mf][3],
                             b[nf][0], b[nf][1]);
        }
    }

    // Epilogue: fp32 to out, bf16 to g_mulbf16[c][b][h]
    const int r0 = lane >> 2;          // 0..7
    const int c0 = (lane & 3) << 1;    // 0,2,4,6
#pragma unroll
    for (int mf = 0; mf < 4; mf++) {
        const int m = bm * 128 + wm * 64 + mf * 16 + r0;
#pragma unroll
        for (int nf = 0; nf < 4; nf++) {
            const int n = bn * 128 + wn * 32 + nf * 8 + c0;
            *(float2*)(out + (size_t)m * 512 + n) =
                make_float2(acc[mf][nf][0], acc[mf][nf][1]);
            *(float2*)(out + (size_t)(m + 8) * 512 + n) =
                make_float2(acc[mf][nf][2], acc[mf][nf][3]);
            // bf16 copies (n is even -> one bf16x2 word each)
            const int b1 = m >> 3, c1 = m & 7;
            const int b2 = (m + 8) >> 3, c2 = c1;
            *(__nv_bfloat162*)(g_mulbf16 + ((size_t)c1 * 1024 + b1) * 512 + n) =
                __halves2bfloat162(__float2bfloat16(acc[mf][nf][0]),
                                   __float2bfloat16(acc[mf][nf][1]));
            *(__nv_bfloat162*)(g_mulbf16 + ((size_t)c2 * 1024 + b2) * 512 + n) =
                __halves2bfloat162(__float2bfloat16(acc[mf][nf][2]),
                                   __float2bfloat16(acc[mf][nf][3]));
        }
    }
}

// ---------------------------------------------------------------------------
// Dot HMMA: g_dot[c][b][k64] = mulbf16[c][b,:] . mubf16[c][k,:]
// Per CTA: c fixed, 64 b-rows x 64 k-cols, K=512 in 8 chunks of 64.
// 4-stage cp.async. <<<128, 256, 73728>>>
// ---------------------------------------------------------------------------
#define DSTRIDE 144
#define DBUF (128 * DSTRIDE)  // 64 A rows + 64 B rows per stage = 18432 B

__global__ void __launch_bounds__(256)
dot_mma_kernel() {
    extern __shared__ __align__(16) char smem[];  // 4 * DBUF
    const uint32_t smem_base = smem_u32(smem);

    const int tid = threadIdx.x;
    const int lane = tid & 31;
    const int wid = tid >> 5;
    const int wm = wid >> 1;    // 0..3 (16-row frags)
    const int wn = wid & 1;     // 0..1 (32-col halves)
    const int c = blockIdx.x & 7;
    const int bt = blockIdx.x >> 3;  // 0..15 (64-row b tiles)

    const __nv_bfloat16* Abase = g_mulbf16 + ((size_t)c * 1024 + bt * 64) * 512;
    const __nv_bfloat16* Bbase = g_mubf16 + (size_t)c * 64 * 512;

    const int lrow = tid >> 3;  // 0..31 (+32)
    const int lseg = tid & 7;   // 0..7 (16B segs of 128B row)

    auto issue = [&](int ch) {
        const int stage = ch & 3;
        const uint32_t sA = smem_base + stage * DBUF;
        const uint32_t sB = sA + 64 * DSTRIDE;
#pragma unroll
        for (int t = 0; t < 2; t++) {
            const int row = lrow + t * 32;
            CP_ASYNC16(sA + row * DSTRIDE + lseg * 16,
                       Abase + (size_t)row * 512 + ch * 64 + lseg * 8);
        }
#pragma unroll
        for (int t = 0; t < 2; t++) {
            const int row = lrow + t * 32;
            CP_ASYNC16(sB + row * DSTRIDE + lseg * 16,
                       Bbase + (size_t)row * 512 + ch * 64 + lseg * 8);
        }
        CP_COMMIT();
    };

    float acc[4][4];
#pragma unroll
    for (int j = 0; j < 4; j++)
#pragma unroll
        for (int q = 0; q < 4; q++) acc[j][q] = 0.f;

    issue(0);
    issue(1);
    issue(2);

    for (int ch = 0; ch < 8; ch++) {
        if (ch <= 5)      asm volatile("cp.async.wait_group 2;" ::: "memory");
        else if (ch == 6) asm volatile("cp.async.wait_group 1;" ::: "memory");
        else              asm volatile("cp.async.wait_group 0;" ::: "memory");
        __syncthreads();
        if (ch + 3 < 8) issue(ch + 3);

        const uint32_t sA = smem_base + (ch & 3) * DBUF;
        const uint32_t sB = sA + 64 * DSTRIDE;
#pragma unroll
        for (int ks = 0; ks < 4; ks++) {
            uint32_t a[4];
            {
                const int row = wm * 16 + (lane & 15);
                const uint32_t col = ks * 32 + ((lane >> 4) << 4);
                ldsm_x4(a[0], a[1], a[2], a[3], sA + row * DSTRIDE + col);
            }
            uint32_t b[4][2];
#pragma unroll
            for (int nf = 0; nf < 4; nf++) {
                const int row = wn * 32 + nf * 8 + (lane & 7);
                const uint32_t col = ks * 32 + (((lane >> 3) & 1) << 4);
                ldsm_x2(b[nf][0], b[nf][1], sB + row * DSTRIDE + col);
            }
#pragma unroll
            for (int nf = 0; nf < 4; nf++)
                mma16816(acc[nf], a[0], a[1], a[2], a[3], b[nf][0], b[nf][1]);
        }
    }

    const int r0 = lane >> 2;
    const int c0 = (lane & 3) << 1;
    const int m = bt * 64 + wm * 16 + r0;
    float* dbase = g_dot + ((size_t)c * 1024 + m) * 64;
#pragma unroll
    for (int nf = 0; nf < 4; nf++) {
        const int n = wn * 32 + nf * 8 + c0;
        *(float2*)(dbase + n) = make_float2(acc[nf][0], acc[nf][1]);
        *(float2*)(dbase + 8 * 64 + n) = make_float2(acc[nf][2], acc[nf][3]);
    }
}

// ---------------------------------------------------------------------------
// Epilogue: fp32 cnorm + distances/k_assign. 4 b-rows per block.
// <<<256, 256>>>
// ---------------------------------------------------------------------------
__global__ void __launch_bounds__(256)
score_epilogue_kernel(const float* __restrict__ mul,
                      float* __restrict__ out_ka, float* __restrict__ out_dist) {
    __shared__ float s_cnorm[32];
    const int tid = threadIdx.x;
    const int lane = tid & 31;
    const int warp = tid >> 5;
    const int b0 = blockIdx.x;  // covers b rows b0*4 .. b0*4+3

    // cnorm for 32 (b,c) rows: warp w handles rows b0*32 + w*4 .. +3
#pragma unroll
    for (int i = 0; i < 4; i++) {
        const int r = b0 * 32 + warp * 4 + i;  // global (b*8+c) row
        const float4* row = (const float4*)(mul + (size_t)r * 512);
        float s = 0.f;
#pragma unroll
        for (int j = lane; j < 128; j += 32) {
            float4 v = row[j];
            s += v.x * v.x + v.y * v.y + v.z * v.z + v.w * v.w;
        }
#pragma unroll
        for (int o = 16; o; o >>= 1) s += __shfl_down_sync(0xffffffffu, s, o);
        if (lane == 0) s_cnorm[warp * 4 + i] = s;
    }
    __syncthreads();

    if (tid < 200) {
        const int bsub = tid / 50;
        const int k = tid % 50;
        const int b = b0 * 4 + bsub;
        float sc[8];
        float S = 0.f;
#pragma unroll
        for (int c = 0; c < 8; c++) {
            const float dot = g_dot[((size_t)c * 1024 + b) * 64 + k];
            const float d2 = 1.f + s_cnorm[bsub * 8 + c] - 2.f * dot
                           + g_munorm[k * 8 + c];
            const float v = 1.f / d2;
            sc[c] = v;
            S += v;
        }
        const float inv1 = 1.f / (S + 1e-8f);
        float dist[8];
        float T = 0.f;
#pragma unroll
        for (int c = 0; c < 8; c++) { dist[c] = sc[c] * inv1; T += dist[c]; }
        const float inv2 = 1.f / T;
        const size_t base = ((size_t)b * 50 + k) << 3;
        float4 d01 = make_float4(dist[0], dist[1], dist[2], dist[3]);
        float4 d23 = make_float4(dist[4], dist[5], dist[6], dist[7]);
        *(float4*)(out_dist + base) = d01;
        *(float4*)(out_dist + base + 4) = d23;
        *(float4*)(out_ka + base) =
            make_float4(d01.x * inv2, d01.y * inv2, d01.z * inv2, d01.w * inv2);
        *(float4*)(out_ka + base + 4) =
            make_float4(d23.x * inv2, d23.y * inv2, d23.z * inv2, d23.w * inv2);
    }
}

// ---------------------------------------------------------------------------
extern "C" void kernel_launch(void* const* d_in, const int* in_sizes, int n_in,
                              void* d_out, int out_size) {
    const float* x        = (const float*)d_in[0];
    const float* class_mu = (const float*)d_in[1];
    const float* mask     = (const float*)d_in[2];
    const float* W        = (const float*)d_in[3];

    float* out      = (float*)d_out;
    float* out_mul  = out;                                  // 1024*8*512
    float* out_ka   = out + (size_t)1024 * 8 * 512;         // 1024*50*8
    float* out_dist = out_ka + (size_t)1024 * 50 * 8;       // 1024*50*8

    const size_t gemm_smem = 4 * BUF_BYTES;  // 81920 B
    const size_t dot_smem  = 4 * DBUF;       // 73728 B
    cudaFuncSetAttribute(mma_gemm_kernel,
                         cudaFuncAttributeMaxDynamicSharedMemorySize, (int)gemm_smem);
    cudaFuncSetAttribute(dot_mma_kernel,
                         cudaFuncAttributeMaxDynamicSharedMemorySize, (int)dot_smem);

    prep_kernel<<<4658, 256>>>(x, mask, W, class_mu);
    mma_gemm_kernel<<<dim3(4, 64), 256, gemm_smem>>>(out_mul);
    dot_mma_kernel<<<128, 256, dot_smem>>>();
    score_epilogue_kernel<<<256, 256>>>(out_mul, out_ka, out_dist);
}

// round 9
// speedup vs baseline: 3.1281x; 1.1600x over previous
#include <cuda_runtime.h>
#include <cuda_bf16.h>
#include <cstdint>
#include <cstddef>

// B=1024, K=50 classes, C=8 centers, H=512
// inputs: d_in[0]=x[1024,512], d_in[1]=class_mu[50,8,512], d_in[2]=mask[8,512], d_in[3]=W[512,512]
// output: concat(mul[1024,8,512] fp32, k_assign[1024,50,8], distances[1024,50,8])
//
// mask is binary {0,1} (jax: (rand > beta).float()), so per-center K-compaction
// of the GEMM (keep only h where mask[c,h]==1) is EXACT. E[|kept|] ~ 256.

// ---------------------------------------------------------------------------
// Scratch (__device__ globals — allocation-free)
// ---------------------------------------------------------------------------
__device__ int   g_kidx[8][512];   // compacted k indices per center (pad = 0)
__device__ int   g_kcnt[8];        // kept count per center
__device__ float g_munorm[400];
// compacted, split A: [c][b][1024]: cols [0,512)=hi(x gathered), [512,1024)=lo
__device__ __align__(16) __nv_bfloat16 g_Axc[8 * 1024 * 1024];
// compacted, split, transposed W: [c][n][1024]: hi | lo
__device__ __align__(16) __nv_bfloat16 g_Wc[8 * 512 * 1024];
// bf16 copy of mul, c-major: [c][b][h]
__device__ __align__(16) __nv_bfloat16 g_mulbf16[8 * 1024 * 512];
// bf16 padded class_mu, c-major: [c][k64][h], zeros for k>=50
__device__ __align__(16) __nv_bfloat16 g_mubf16[8 * 64 * 512];
// dot products: [c][b][k64] fp32
__device__ __align__(16) float g_dot[8 * 1024 * 64];
// per-bn partial ||mul[b,c]||^2: [bn][c*1024+b]
__device__ float g_cnormp[4][8 * 1024];

// ---------------------------------------------------------------------------
// PTX helpers (baseline sm_103 target — no 'a'-suffix features)
// ---------------------------------------------------------------------------
__device__ __forceinline__ uint32_t smem_u32(const void* p) {
    uint32_t a;
    asm("{ .reg .u64 t; cvta.to.shared.u64 t, %1; cvt.u32.u64 %0, t; }"
        : "=r"(a) : "l"(p));
    return a;
}

__device__ __forceinline__ void ldsm_x4(uint32_t& r0, uint32_t& r1, uint32_t& r2,
                                        uint32_t& r3, uint32_t addr) {
    asm volatile("ldmatrix.sync.aligned.m8n8.x4.shared.b16 {%0,%1,%2,%3}, [%4];"
                 : "=r"(r0), "=r"(r1), "=r"(r2), "=r"(r3) : "r"(addr));
}

__device__ __forceinline__ void ldsm_x2(uint32_t& r0, uint32_t& r1, uint32_t addr) {
    asm volatile("ldmatrix.sync.aligned.m8n8.x2.shared.b16 {%0,%1}, [%2];"
                 : "=r"(r0), "=r"(r1) : "r"(addr));
}

__device__ __forceinline__ void mma16816(float* c, uint32_t a0, uint32_t a1,
                                         uint32_t a2, uint32_t a3,
                                         uint32_t b0, uint32_t b1) {
    asm volatile(
        "mma.sync.aligned.m16n8k16.row.col.f32.bf16.bf16.f32 "
        "{%0,%1,%2,%3}, {%4,%5,%6,%7}, {%8,%9}, {%0,%1,%2,%3};"
        : "+f"(c[0]), "+f"(c[1]), "+f"(c[2]), "+f"(c[3])
        : "r"(a0), "r"(a1), "r"(a2), "r"(a3), "r"(b0), "r"(b1));
}

#define CP_ASYNC16(dst, src) \
    asm volatile("cp.async.cg.shared.global [%0], [%1], 16;" \
                 :: "r"(dst), "l"(src) : "memory")
#define CP_COMMIT() asm volatile("cp.async.commit_group;" ::: "memory")

// ---------------------------------------------------------------------------
// Setup: per-center mask compaction (ballot + prefix scan). <<<1, 512>>>
// ---------------------------------------------------------------------------
__global__ void setup_kernel(const float* __restrict__ mask) {
    __shared__ int wsum[16];
    __shared__ int s_total;
    const int tid = threadIdx.x;
    const int lane = tid & 31;
    const int warp = tid >> 5;
    for (int c = 0; c < 8; c++) {
        const int pred = (mask[c * 512 + tid] != 0.f) ? 1 : 0;
        const unsigned bal = __ballot_sync(0xffffffffu, pred);
        const int lpos = __popc(bal & ((1u << lane) - 1u));
        if (lane == 0) wsum[warp] = __popc(bal);
        __syncthreads();
        int wbase = 0;
        for (int w = 0; w < warp; w++) wbase += wsum[w];
        if (pred) g_kidx[c][wbase + lpos] = tid;
        if (tid == 0) {
            int t = 0;
            for (int w = 0; w < 16; w++) t += wsum[w];
            g_kcnt[c] = t;
            s_total = t;
        }
        __syncthreads();
        if (tid >= s_total) g_kidx[c][tid] = 0;  // pad (guarded by j<kcnt later)
        __syncthreads();
    }
}

// ---------------------------------------------------------------------------
// Prep: gather+split A | gather+transpose+split W | munorm | class_mu->bf16
// grid = 8192 + 2048 + 50 + 256 = 10546, 256 threads
// ---------------------------------------------------------------------------
__global__ void prep_kernel(const float* __restrict__ x,
                            const float* __restrict__ W,
                            const float* __restrict__ class_mu) {
    __shared__ float tile[32][33];
    const int tid = threadIdx.x;
    const int blk = blockIdx.x;

    if (blk < 8192) {
        // ---- gather + split A: Axc[c][b][j] = split(x[b][kidx[c][j]]) ----
        const int c = blk >> 10, b = blk & 1023;
        const int kcnt = g_kcnt[c];
        const int nch32 = ((kcnt + 31) >> 5) << 5;
        const int j2 = tid * 2;
        if (j2 < nch32) {
            const int i0 = g_kidx[c][j2];
            const int i1 = g_kidx[c][j2 + 1];
            const float v0 = (j2 < kcnt) ? x[(size_t)b * 512 + i0] : 0.f;
            const float v1 = (j2 + 1 < kcnt) ? x[(size_t)b * 512 + i1] : 0.f;
            const __nv_bfloat16 h0 = __float2bfloat16(v0);
            const __nv_bfloat16 h1 = __float2bfloat16(v1);
            const __nv_bfloat16 l0 = __float2bfloat16(v0 - __bfloat162float(h0));
            const __nv_bfloat16 l1 = __float2bfloat16(v1 - __bfloat162float(h1));
            __nv_bfloat16* base = g_Axc + (((size_t)c * 1024 + b) << 10);
            *(__nv_bfloat162*)(base + j2)       = __halves2bfloat162(h0, h1);
            *(__nv_bfloat162*)(base + 512 + j2) = __halves2bfloat162(l0, l1);
        }
    } else if (blk < 8192 + 2048) {
        // ---- gather + transpose + split W: Wc[c][n][j] = split(W[kidx[c][j]][n]) ----
        const int t = blk - 8192;
        const int c = t >> 8;
        const int jt = (t >> 4) & 15, nt = t & 15;
        const int kcnt = g_kcnt[c];
        const int nch32 = ((kcnt + 31) >> 5) << 5;
        if (jt * 32 >= nch32) return;
        const int tx = tid & 31, ty = tid >> 5;  // tx=n_local, ty=j_row base
#pragma unroll
        for (int i = 0; i < 32; i += 8) {
            const int j = jt * 32 + ty + i;
            const float v = (j < kcnt)
                ? W[(size_t)g_kidx[c][j] * 512 + nt * 32 + tx] : 0.f;
            tile[ty + i][tx] = v;
        }
        __syncthreads();
#pragma unroll
        for (int i = 0; i < 32; i += 8) {
            const int n = nt * 32 + ty + i;
            const int j = jt * 32 + tx;
            const float v = tile[tx][ty + i];
            const __nv_bfloat16 hi = __float2bfloat16(v);
            const __nv_bfloat16 lo = __float2bfloat16(v - __bfloat162float(hi));
            __nv_bfloat16* base = g_Wc + (((size_t)c * 512 + n) << 10);
            base[j] = hi;
            base[512 + j] = lo;
        }
    } else if (blk < 8192 + 2048 + 50) {
        // ---- munorm ----
        const int warp = tid >> 5;
        const int lane = tid & 31;
        const int r = (blk - 10240) * 8 + warp;  // 0..399
        const float4* row = (const float4*)(class_mu + (size_t)r * 512);
        float s = 0.f;
#pragma unroll
        for (int j = lane; j < 128; j += 32) {
            float4 v = row[j];
            s += v.x * v.x + v.y * v.y + v.z * v.z + v.w * v.w;
        }
#pragma unroll
        for (int o = 16; o; o >>= 1) s += __shfl_down_sync(0xffffffffu, s, o);
        if (lane == 0) g_munorm[r] = s;
    } else {
        // ---- class_mu -> g_mubf16[c][k64][h], zero padded ----
        const int t = blk - 10290;
        const int idx4 = t * 256 + tid;          // 0..65535 (x4 elems)
        const int row = idx4 >> 7;               // 0..511 = c*64+k
        const int h = (idx4 & 127) << 2;
        const int c = row >> 6, k = row & 63;
        float4 v = make_float4(0.f, 0.f, 0.f, 0.f);
        if (k < 50) v = *(const float4*)(class_mu + (((size_t)k * 8 + c) << 9) + h);
        __nv_bfloat162* dst = (__nv_bfloat162*)(g_mubf16 + (size_t)row * 512 + h);
        dst[0] = __halves2bfloat162(__float2bfloat16(v.x), __float2bfloat16(v.y));
        dst[1] = __halves2bfloat162(__float2bfloat16(v.z), __float2bfloat16(v.w));
    }
}

// ---------------------------------------------------------------------------
// K-compacted HMMA GEMM, per-center: mul[b,c,:] = Axc[c] @ Wc[c]^T
// virtual K = 3 * Kpad(c)  (A: hi,hi,lo x B: hi,lo,hi), Kpad ~ 256.
// CTA tile 128x128, warp tile 64x32, K-chunk 32, 4-stage cp.async.
// Epilogue: fp32 out + bf16 g_mulbf16[c][b][h] + partial cnorm.
// <<<dim3(4, 64), 256, 81920>>>, blockIdx.y = c*8 + bm
// ---------------------------------------------------------------------------
#define SM_STRIDE 80
#define BUF_BYTES 20480  // (128 rows A + 128 rows B) * 80B

__global__ void __launch_bounds__(256, 2)
mma_gemm_kernel(float* __restrict__ out) {
    extern __shared__ __align__(16) char smem[];  // 4 * BUF_BYTES
    __shared__ float s_part[4][128];
    const uint32_t smem_base = smem_u32(smem);

    const int tid = threadIdx.x;
    const int lane = tid & 31;
    const int wid = tid >> 5;
    const int wm = wid >> 2;          // 0..1
    const int wn = wid & 3;           // 0..3
    const int bn = blockIdx.x;        // 0..3 (128-col n tiles)
    const int c  = blockIdx.y >> 3;   // 0..7
    const int bm = blockIdx.y & 7;    // 0..7 (128-row b tiles)

    const int kcnt = g_kcnt[c];
    const int nch = (kcnt + 31) >> 5;     // chunks per pass (<=16)
    const int T = 3 * nch;                // total chunks

    const __nv_bfloat16* Abase = g_Axc + (((size_t)c * 1024 + bm * 128) << 10);
    const __nv_bfloat16* Bbase = g_Wc  + (((size_t)c * 512  + bn * 128) << 10);

    const int lrow = tid >> 2;  // 0..63 (+64 second half)
    const int lseg = tid & 3;   // 0..3

    auto issue = [&](int t) {
        const int stage = t & 3;
        const int p = (t >= 2 * nch) ? 2 : ((t >= nch) ? 1 : 0);
        const int sub = t - p * nch;
        const int acol = ((p == 2) ? 512 : 0) + sub * 32;  // A: hi,hi,lo
        const int bcol = ((p == 1) ? 512 : 0) + sub * 32;  // B: hi,lo,hi
        const uint32_t sA = smem_base + stage * BUF_BYTES;
        const uint32_t sB = sA + 128 * SM_STRIDE;
#pragma unroll
        for (int q = 0; q < 2; q++) {
            const int row = lrow + q * 64;
            CP_ASYNC16(sA + row * SM_STRIDE + lseg * 16,
                       Abase + ((size_t)row << 10) + acol + lseg * 8);
        }
#pragma unroll
        for (int q = 0; q < 2; q++) {
            const int row = lrow + q * 64;
            CP_ASYNC16(sB + row * SM_STRIDE + lseg * 16,
                       Bbase + ((size_t)row << 10) + bcol + lseg * 8);
        }
        CP_COMMIT();
    };

    float acc[4][4][4];
#pragma unroll
    for (int i = 0; i < 4; i++)
#pragma unroll
        for (int j = 0; j < 4; j++)
#pragma unroll
            for (int q = 0; q < 4; q++) acc[i][j][q] = 0.f;

    issue(0);
    issue(1);
    issue(2);

    for (int t = 0; t < T; t++) {
        if (t <= T - 3)      asm volatile("cp.async.wait_group 2;" ::: "memory");
        else if (t == T - 2) asm volatile("cp.async.wait_group 1;" ::: "memory");
        else                 asm volatile("cp.async.wait_group 0;" ::: "memory");
        __syncthreads();
        if (t + 3 < T) issue(t + 3);

        const uint32_t sA = smem_base + (t & 3) * BUF_BYTES;
        const uint32_t sB = sA + 128 * SM_STRIDE;
#pragma unroll
        for (int ks = 0; ks < 2; ks++) {
            uint32_t a[4][4];
#pragma unroll
            for (int mf = 0; mf < 4; mf++) {
                const int row = wm * 64 + mf * 16 + (lane & 15);
                const uint32_t col = ks * 32 + ((lane >> 4) << 4);
                ldsm_x4(a[mf][0], a[mf][1], a[mf][2], a[mf][3],
                        sA + row * SM_STRIDE + col);
            }
            uint32_t b[4][2];
#pragma unroll
            for (int nf = 0; nf < 4; nf++) {
                const int row = wn * 32 + nf * 8 + (lane & 7);
                const uint32_t col = ks * 32 + (((lane >> 3) & 1) << 4);
                ldsm_x2(b[nf][0], b[nf][1], sB + row * SM_STRIDE + col);
            }
#pragma unroll
            for (int mf = 0; mf < 4; mf++)
#pragma unroll
                for (int nf = 0; nf < 4; nf++)
                    mma16816(acc[mf][nf], a[mf][0], a[mf][1], a[mf][2], a[mf][3],
                             b[nf][0], b[nf][1]);
        }
    }

    // ---- Epilogue 1: stores (fp32 out, bf16 c-major copy) ----
    const int r0 = lane >> 2;          // 0..7
    const int c0 = (lane & 3) << 1;    // 0,2,4,6
#pragma unroll
    for (int mf = 0; mf < 4; mf++) {
        const int bl = bm * 128 + wm * 64 + mf * 16 + r0;  // batch row
#pragma unroll
        for (int nf = 0; nf < 4; nf++) {
            const int n = bn * 128 + wn * 32 + nf * 8 + c0;
            *(float2*)(out + (((size_t)bl * 8 + c) << 9) + n) =
                make_float2(acc[mf][nf][0], acc[mf][nf][1]);
            *(float2*)(out + (((size_t)(bl + 8) * 8 + c) << 9) + n) =
                make_float2(acc[mf][nf][2], acc[mf][nf][3]);
            *(__nv_bfloat162*)(g_mulbf16 + (((size_t)c * 1024 + bl) << 9) + n) =
                __halves2bfloat162(__float2bfloat16(acc[mf][nf][0]),
                                   __float2bfloat16(acc[mf][nf][1]));
            *(__nv_bfloat162*)(g_mulbf16 + (((size_t)c * 1024 + bl + 8) << 9) + n) =
                __halves2bfloat162(__float2bfloat16(acc[mf][nf][2]),
                                   __float2bfloat16(acc[mf][nf][3]));
        }
    }

    // ---- Epilogue 2: partial cnorm over this CTA's 128 n-cols ----
#pragma unroll
    for (int mf = 0; mf < 4; mf++) {
        float p1 = 0.f, p2 = 0.f;
#pragma unroll
        for (int nf = 0; nf < 4; nf++) {
            p1 += acc[mf][nf][0] * acc[mf][nf][0] + acc[mf][nf][1] * acc[mf][nf][1];
            p2 += acc[mf][nf][2] * acc[mf][nf][2] + acc[mf][nf][3] * acc[mf][nf][3];
        }
        p1 += __shfl_xor_sync(0xffffffffu, p1, 1);
        p1 += __shfl_xor_sync(0xffffffffu, p1, 2);
        p2 += __shfl_xor_sync(0xffffffffu, p2, 1);
        p2 += __shfl_xor_sync(0xffffffffu, p2, 2);
        if ((lane & 3) == 0) {
            s_part[wn][wm * 64 + mf * 16 + r0] = p1;
            s_part[wn][wm * 64 + mf * 16 + r0 + 8] = p2;
        }
    }
    __syncthreads();
    if (tid < 128) {
        const float cn = s_part[0][tid] + s_part[1][tid]
                       + s_part[2][tid] + s_part[3][tid];
        g_cnormp[bn][c * 1024 + bm * 128 + tid] = cn;
    }
}

// ---------------------------------------------------------------------------
// Dot HMMA: g_dot[c][b][k64] = mulbf16[c][b,:] . mubf16[c][k,:]
// <<<128, 256, 73728>>>
// ---------------------------------------------------------------------------
#define DSTRIDE 144
#define DBUF (128 * DSTRIDE)

__global__ void __launch_bounds__(256)
dot_mma_kernel() {
    extern __shared__ __align__(16) char smem[];  // 4 * DBUF
    const uint32_t smem_base = smem_u32(smem);

    const int tid = threadIdx.x;
    const int lane = tid & 31;
    const int wid = tid >> 5;
    const int wm = wid >> 1;    // 0..3
    const int wn = wid & 1;     // 0..1
    const int c = blockIdx.x & 7;
    const int bt = blockIdx.x >> 3;  // 0..15

    const __nv_bfloat16* Abase = g_mulbf16 + (((size_t)c * 1024 + bt * 64) << 9);
    const __nv_bfloat16* Bbase = g_mubf16 + ((size_t)c << 15);

    const int lrow = tid >> 3;
    const int lseg = tid & 7;

    auto issue = [&](int ch) {
        const int stage = ch & 3;
        const uint32_t sA = smem_base + stage * DBUF;
        const uint32_t sB = sA + 64 * DSTRIDE;
#pragma unroll
        for (int q = 0; q < 2; q++) {
            const int row = lrow + q * 32;
            CP_ASYNC16(sA + row * DSTRIDE + lseg * 16,
                       Abase + ((size_t)row << 9) + ch * 64 + lseg * 8);
        }
#pragma unroll
        for (int q = 0; q < 2; q++) {
            const int row = lrow + q * 32;
            CP_ASYNC16(sB + row * DSTRIDE + lseg * 16,
                       Bbase + ((size_t)row << 9) + ch * 64 + lseg * 8);
        }
        CP_COMMIT();
    };

    float acc[4][4];
#pragma unroll
    for (int j = 0; j < 4; j++)
#pragma unroll
        for (int q = 0; q < 4; q++) acc[j][q] = 0.f;

    issue(0);
    issue(1);
    issue(2);

    for (int ch = 0; ch < 8; ch++) {
        if (ch <= 5)      asm volatile("cp.async.wait_group 2;" ::: "memory");
        else if (ch == 6) asm volatile("cp.async.wait_group 1;" ::: "memory");
        else              asm volatile("cp.async.wait_group 0;" ::: "memory");
        __syncthreads();
        if (ch + 3 < 8) issue(ch + 3);

        const uint32_t sA = smem_base + (ch & 3) * DBUF;
        const uint32_t sB = sA + 64 * DSTRIDE;
#pragma unroll
        for (int ks = 0; ks < 4; ks++) {
            uint32_t a[4];
            {
                const int row = wm * 16 + (lane & 15);
                const uint32_t col = ks * 32 + ((lane >> 4) << 4);
                ldsm_x4(a[0], a[1], a[2], a[3], sA + row * DSTRIDE + col);
            }
            uint32_t b[4][2];
#pragma unroll
            for (int nf = 0; nf < 4; nf++) {
                const int row = wn * 32 + nf * 8 + (lane & 7);
                const uint32_t col = ks * 32 + (((lane >> 3) & 1) << 4);
                ldsm_x2(b[nf][0], b[nf][1], sB + row * DSTRIDE + col);
            }
#pragma unroll
            for (int nf = 0; nf < 4; nf++)
                mma16816(acc[nf], a[0], a[1], a[2], a[3], b[nf][0], b[nf][1]);
        }
    }

    const int r0 = lane >> 2;
    const int c0 = (lane & 3) << 1;
    const int m = bt * 64 + wm * 16 + r0;
    float* dbase = g_dot + (((size_t)c * 1024 + m) << 6);
#pragma unroll
    for (int nf = 0; nf < 4; nf++) {
        const int n = wn * 32 + nf * 8 + c0;
        *(float2*)(dbase + n) = make_float2(acc[nf][0], acc[nf][1]);
        *(float2*)(dbase + (8 << 6) + n) = make_float2(acc[nf][2], acc[nf][3]);
    }
}

// ---------------------------------------------------------------------------
// Epilogue: distances/k_assign from precomputed cnorm partials + dots.
// <<<256, 256>>>
// ---------------------------------------------------------------------------
__global__ void __launch_bounds__(256)
score_epilogue_kernel(float* __restrict__ out_ka, float* __restrict__ out_dist) {
    __shared__ float s_cnorm[32];
    const int tid = threadIdx.x;
    const int b0 = blockIdx.x;  // covers b rows b0*4 .. b0*4+3

    if (tid < 32) {
        const int bsub = tid >> 3, cc = tid & 7;
        const int b = b0 * 4 + bsub;
        s_cnorm[bsub * 8 + cc] = g_cnormp[0][cc * 1024 + b]
                               + g_cnormp[1][cc * 1024 + b]
                               + g_cnormp[2][cc * 1024 + b]
                               + g_cnormp[3][cc * 1024 + b];
    }
    __syncthreads();

    if (tid < 200) {
        const int bsub = tid / 50;
        const int k = tid % 50;
        const int b = b0 * 4 + bsub;
        float sc[8];
        float S = 0.f;
#pragma unroll
        for (int c = 0; c < 8; c++) {
            const float dot = g_dot[(((size_t)c * 1024 + b) << 6) + k];
            const float d2 = 1.f + s_cnorm[bsub * 8 + c] - 2.f * dot
                           + g_munorm[k * 8 + c];
            const float v = 1.f / d2;
            sc[c] = v;
            S += v;
        }
        const float inv1 = 1.f / (S + 1e-8f);
        float dist[8];
        float T = 0.f;
#pragma unroll
        for (int c = 0; c < 8; c++) { dist[c] = sc[c] * inv1; T += dist[c]; }
        const float inv2 = 1.f / T;
        const size_t base = ((size_t)b * 50 + k) << 3;
        float4 d01 = make_float4(dist[0], dist[1], dist[2], dist[3]);
        float4 d23 = make_float4(dist[4], dist[5], dist[6], dist[7]);
        *(float4*)(out_dist + base) = d01;
        *(float4*)(out_dist + base + 4) = d23;
        *(float4*)(out_ka + base) =
            make_float4(d01.x * inv2, d01.y * inv2, d01.z * inv2, d01.w * inv2);
        *(float4*)(out_ka + base + 4) =
            make_float4(d23.x * inv2, d23.y * inv2, d23.z * inv2, d23.w * inv2);
    }
}

// ---------------------------------------------------------------------------
extern "C" void kernel_launch(void* const* d_in, const int* in_sizes, int n_in,
                              void* d_out, int out_size) {
    const float* x        = (const float*)d_in[0];
    const float* class_mu = (const float*)d_in[1];
    const float* mask     = (const float*)d_in[2];
    const float* W        = (const float*)d_in[3];

    float* out      = (float*)d_out;
    float* out_mul  = out;                                  // 1024*8*512
    float* out_ka   = out + (size_t)1024 * 8 * 512;         // 1024*50*8
    float* out_dist = out_ka + (size_t)1024 * 50 * 8;       // 1024*50*8

    const size_t gemm_smem = 4 * BUF_BYTES;  // 81920 B
    const size_t dot_smem  = 4 * DBUF;       // 73728 B
    cudaFuncSetAttribute(mma_gemm_kernel,
                         cudaFuncAttributeMaxDynamicSharedMemorySize, (int)gemm_smem);
    cudaFuncSetAttribute(dot_mma_kernel,
                         cudaFuncAttributeMaxDynamicSharedMemorySize, (int)dot_smem);

    setup_kernel<<<1, 512>>>(mask);
    prep_kernel<<<10546, 256>>>(x, W, class_mu);
    mma_gemm_kernel<<<dim3(4, 64), 256, gemm_smem>>>(out_mul);
    dot_mma_kernel<<<128, 256, dot_smem>>>();
    score_epilogue_kernel<<<256, 256>>>(out_ka, out_dist);
}

// round 10
// speedup vs baseline: 3.3504x; 1.0711x over previous
#include <cuda_runtime.h>
#include <cuda_bf16.h>
#include <cstdint>
#include <cstddef>

// B=1024, K=50 classes, C=8 centers, H=512
// inputs: d_in[0]=x[1024,512], d_in[1]=class_mu[50,8,512], d_in[2]=mask[8,512], d_in[3]=W[512,512]
// output: concat(mul[1024,8,512] fp32, k_assign[1024,50,8], distances[1024,50,8])
//
// mask is binary {0,1} => per-center K-compaction of the GEMM is EXACT.

// ---------------------------------------------------------------------------
// Scratch (__device__ globals — allocation-free)
// ---------------------------------------------------------------------------
__device__ int   g_kcnt[8];        // kept count per center
__device__ float g_munorm[400];
// compacted, split A: [c][b][1024]: cols [0,512)=hi(x gathered), [512,1024)=lo
__device__ __align__(16) __nv_bfloat16 g_Axc[8 * 1024 * 1024];
// compacted, split, transposed W: [c][n][1024]: hi | lo
__device__ __align__(16) __nv_bfloat16 g_Wc[8 * 512 * 1024];
// bf16 copy of mul, c-major: [c][b][h]
__device__ __align__(16) __nv_bfloat16 g_mulbf16[8 * 1024 * 512];
// bf16 padded class_mu, c-major: [c][k64][h], zeros for k>=50
__device__ __align__(16) __nv_bfloat16 g_mubf16[8 * 64 * 512];
// dot partials: [half][c][b][k64] fp32
__device__ __align__(16) float g_dotp[2][8 * 1024 * 64];
// per-bn partial ||mul[b,c]||^2: [bn][c*1024+b]
__device__ float g_cnormp[4][8 * 1024];

// ---------------------------------------------------------------------------
// PTX helpers (baseline sm_103 target — no 'a'-suffix features)
// ---------------------------------------------------------------------------
__device__ __forceinline__ uint32_t smem_u32(const void* p) {
    uint32_t a;
    asm("{ .reg .u64 t; cvta.to.shared.u64 t, %1; cvt.u32.u64 %0, t; }"
        : "=r"(a) : "l"(p));
    return a;
}

__device__ __forceinline__ void ldsm_x4(uint32_t& r0, uint32_t& r1, uint32_t& r2,
                                        uint32_t& r3, uint32_t addr) {
    asm volatile("ldmatrix.sync.aligned.m8n8.x4.shared.b16 {%0,%1,%2,%3}, [%4];"
                 : "=r"(r0), "=r"(r1), "=r"(r2), "=r"(r3) : "r"(addr));
}

__device__ __forceinline__ void ldsm_x2(uint32_t& r0, uint32_t& r1, uint32_t addr) {
    asm volatile("ldmatrix.sync.aligned.m8n8.x2.shared.b16 {%0,%1}, [%2];"
                 : "=r"(r0), "=r"(r1) : "r"(addr));
}

__device__ __forceinline__ void mma16816(float* c, uint32_t a0, uint32_t a1,
                                         uint32_t a2, uint32_t a3,
                                         uint32_t b0, uint32_t b1) {
    asm volatile(
        "mma.sync.aligned.m16n8k16.row.col.f32.bf16.bf16.f32 "
        "{%0,%1,%2,%3}, {%4,%5,%6,%7}, {%8,%9}, {%0,%1,%2,%3};"
        : "+f"(c[0]), "+f"(c[1]), "+f"(c[2]), "+f"(c[3])
        : "r"(a0), "r"(a1), "r"(a2), "r"(a3), "r"(b0), "r"(b1));
}

#define CP_ASYNC16(dst, src) \
    asm volatile("cp.async.cg.shared.global [%0], [%1], 16;" \
                 :: "r"(dst), "l"(src) : "memory")
#define CP_COMMIT() asm volatile("cp.async.commit_group;" ::: "memory")

// ---------------------------------------------------------------------------
// In-block mask compaction: 256 threads, warp w owns elements [w*64, w*64+64).
// Produces ascending compacted indices in s_kidx (padded 0 up to 512).
// Returns total kept count. Contains 2 __syncthreads (all threads must call).
// ---------------------------------------------------------------------------
__device__ __forceinline__ int compact_mask(const float* __restrict__ mask_row,
                                            int tid, int* s_kidx, int* s_wcnt) {
    const int lane = tid & 31;
    const int warp = tid >> 5;  // 0..7
    const int e0 = warp * 64 + lane;
    const int e1 = e0 + 32;
    const int p0 = (mask_row[e0] != 0.f) ? 1 : 0;
    const int p1 = (mask_row[e1] != 0.f) ? 1 : 0;
    const unsigned b0 = __ballot_sync(0xffffffffu, p0);
    const unsigned b1 = __ballot_sync(0xffffffffu, p1);
    const int c0 = __popc(b0);
    if (lane == 0) s_wcnt[warp] = c0 + __popc(b1);
    __syncthreads();
    int base = 0, total = 0;
#pragma unroll
    for (int w = 0; w < 8; w++) {
        if (w < warp) base += s_wcnt[w];
        total += s_wcnt[w];
    }
    if (p0) s_kidx[base + __popc(b0 & ((1u << lane) - 1u))] = e0;
    if (p1) s_kidx[base + c0 + __popc(b1 & ((1u << lane) - 1u))] = e1;
    for (int j = total + tid; j < 512; j += 256) s_kidx[j] = 0;
    __syncthreads();
    return total;
}

// ---------------------------------------------------------------------------
// Prep: gather+split A (4 rows/blk) | gather+transpose+split W | munorm | mubf16
// grid = 2048 + 2048 + 50 + 256 = 4402, 256 threads
// ---------------------------------------------------------------------------
__global__ void prep_kernel(const float* __restrict__ x,
                            const float* __restrict__ mask,
                            const float* __restrict__ W,
                            const float* __restrict__ class_mu) {
    __shared__ int s_kidx[512];
    __shared__ int s_wcnt[8];
    __shared__ float s_x[4][512];
    __shared__ float tile[32][33];
    const int tid = threadIdx.x;
    const int blk = blockIdx.x;

    if (blk < 2048) {
        // ---- gather + split A: 4 b-rows per block ----
        const int c = blk >> 8;          // 0..7
        const int bq = blk & 255;        // 0..255 -> rows bq*4..+3
        // stage x rows coalesced (before barrier inside compact_mask is fine:
        // loads are issued, consumed after the final barrier)
        for (int i = tid; i < 4 * 512; i += 256)
            s_x[i >> 9][i & 511] = x[(size_t)(bq * 4 + (i >> 9)) * 512 + (i & 511)];
        const int total = compact_mask(mask + c * 512, tid, s_kidx, s_wcnt);
        if (bq == 0 && tid == 0) g_kcnt[c] = total;
        const int nch32 = ((total + 31) >> 5) << 5;
        const int j2 = tid * 2;
        if (j2 < nch32) {
            const int i0 = s_kidx[j2];
            const int i1 = s_kidx[j2 + 1];
            const bool v0ok = j2 < total, v1ok = (j2 + 1) < total;
#pragma unroll
            for (int r = 0; r < 4; r++) {
                const float v0 = v0ok ? s_x[r][i0] : 0.f;
                const float v1 = v1ok ? s_x[r][i1] : 0.f;
                const __nv_bfloat16 h0 = __float2bfloat16(v0);
                const __nv_bfloat16 h1 = __float2bfloat16(v1);
                const __nv_bfloat16 l0 = __float2bfloat16(v0 - __bfloat162float(h0));
                const __nv_bfloat16 l1 = __float2bfloat16(v1 - __bfloat162float(h1));
                __nv_bfloat16* base =
                    g_Axc + (((size_t)c * 1024 + bq * 4 + r) << 10);
                *(__nv_bfloat162*)(base + j2)       = __halves2bfloat162(h0, h1);
                *(__nv_bfloat162*)(base + 512 + j2) = __halves2bfloat162(l0, l1);
            }
        }
    } else if (blk < 4096) {
        // ---- gather + transpose + split W ----
        const int t = blk - 2048;
        const int c = t >> 8;
        const int jt = (t >> 4) & 15, nt = t & 15;
        const int total = compact_mask(mask + c * 512, tid, s_kidx, s_wcnt);
        const int nch32 = ((total + 31) >> 5) << 5;
        if (jt * 32 >= nch32) return;
        const int tx = tid & 31, ty = tid >> 5;
#pragma unroll
        for (int i = 0; i < 32; i += 8) {
            const int j = jt * 32 + ty + i;
            tile[ty + i][tx] = (j < total)
                ? W[(size_t)s_kidx[j] * 512 + nt * 32 + tx] : 0.f;
        }
        __syncthreads();
#pragma unroll
        for (int i = 0; i < 32; i += 8) {
            const int n = nt * 32 + ty + i;
            const int j = jt * 32 + tx;
            const float v = tile[tx][ty + i];
            const __nv_bfloat16 hi = __float2bfloat16(v);
            const __nv_bfloat16 lo = __float2bfloat16(v - __bfloat162float(hi));
            __nv_bfloat16* base = g_Wc + (((size_t)c * 512 + n) << 10);
            base[j] = hi;
            base[512 + j] = lo;
        }
    } else if (blk < 4096 + 50) {
        // ---- munorm ----
        const int warp = tid >> 5;
        const int lane = tid & 31;
        const int r = (blk - 4096) * 8 + warp;  // 0..399
        const float4* row = (const float4*)(class_mu + (size_t)r * 512);
        float s = 0.f;
#pragma unroll
        for (int j = lane; j < 128; j += 32) {
            float4 v = row[j];
            s += v.x * v.x + v.y * v.y + v.z * v.z + v.w * v.w;
        }
#pragma unroll
        for (int o = 16; o; o >>= 1) s += __shfl_down_sync(0xffffffffu, s, o);
        if (lane == 0) g_munorm[r] = s;
    } else {
        // ---- class_mu -> g_mubf16[c][k64][h], zero padded ----
        const int t = blk - 4146;
        const int idx4 = t * 256 + tid;          // 0..65535 (x4 elems)
        const int row = idx4 >> 7;               // 0..511 = c*64+k
        const int h = (idx4 & 127) << 2;
        const int c = row >> 6, k = row & 63;
        float4 v = make_float4(0.f, 0.f, 0.f, 0.f);
        if (k < 50) v = *(const float4*)(class_mu + (((size_t)k * 8 + c) << 9) + h);
        __nv_bfloat162* dst = (__nv_bfloat162*)(g_mubf16 + (size_t)row * 512 + h);
        dst[0] = __halves2bfloat162(__float2bfloat16(v.x), __float2bfloat16(v.y));
        dst[1] = __halves2bfloat162(__float2bfloat16(v.z), __float2bfloat16(v.w));
    }
}

// ---------------------------------------------------------------------------
// K-compacted HMMA GEMM, per-center: mul[b,c,:] = Axc[c] @ Wc[c]^T
// virtual K = 3 * Kpad(c). CTA tile 128x128, warp tile 64x32, 4-stage cp.async.
// Epilogue: fp32 out + bf16 g_mulbf16 + partial cnorm.
// <<<dim3(4, 64), 256, 81920>>>, blockIdx.y = c*8 + bm
// ---------------------------------------------------------------------------
#define SM_STRIDE 80
#define BUF_BYTES 20480

__global__ void __launch_bounds__(256, 2)
mma_gemm_kernel(float* __restrict__ out) {
    extern __shared__ __align__(16) char smem[];  // 4 * BUF_BYTES
    __shared__ float s_part[4][128];
    const uint32_t smem_base = smem_u32(smem);

    const int tid = threadIdx.x;
    const int lane = tid & 31;
    const int wid = tid >> 5;
    const int wm = wid >> 2;
    const int wn = wid & 3;
    const int bn = blockIdx.x;
    const int c  = blockIdx.y >> 3;
    const int bm = blockIdx.y & 7;

    const int kcnt = g_kcnt[c];
    const int nch = (kcnt + 31) >> 5;
    const int T = 3 * nch;

    const __nv_bfloat16* Abase = g_Axc + (((size_t)c * 1024 + bm * 128) << 10);
    const __nv_bfloat16* Bbase = g_Wc  + (((size_t)c * 512  + bn * 128) << 10);

    const int lrow = tid >> 2;
    const int lseg = tid & 3;

    auto issue = [&](int t) {
        const int stage = t & 3;
        const int p = (t >= 2 * nch) ? 2 : ((t >= nch) ? 1 : 0);
        const int sub = t - p * nch;
        const int acol = ((p == 2) ? 512 : 0) + sub * 32;  // A: hi,hi,lo
        const int bcol = ((p == 1) ? 512 : 0) + sub * 32;  // B: hi,lo,hi
        const uint32_t sA = smem_base + stage * BUF_BYTES;
        const uint32_t sB = sA + 128 * SM_STRIDE;
#pragma unroll
        for (int q = 0; q < 2; q++) {
            const int row = lrow + q * 64;
            CP_ASYNC16(sA + row * SM_STRIDE + lseg * 16,
                       Abase + ((size_t)row << 10) + acol + lseg * 8);
        }
#pragma unroll
        for (int q = 0; q < 2; q++) {
            const int row = lrow + q * 64;
            CP_ASYNC16(sB + row * SM_STRIDE + lseg * 16,
                       Bbase + ((size_t)row << 10) + bcol + lseg * 8);
        }
        CP_COMMIT();
    };

    float acc[4][4][4];
#pragma unroll
    for (int i = 0; i < 4; i++)
#pragma unroll
        for (int j = 0; j < 4; j++)
#pragma unroll
            for (int q = 0; q < 4; q++) acc[i][j][q] = 0.f;

    issue(0);
    issue(1);
    issue(2);

    for (int t = 0; t < T; t++) {
        if (t <= T - 3)      asm volatile("cp.async.wait_group 2;" ::: "memory");
        else if (t == T - 2) asm volatile("cp.async.wait_group 1;" ::: "memory");
        else                 asm volatile("cp.async.wait_group 0;" ::: "memory");
        __syncthreads();
        if (t + 3 < T) issue(t + 3);

        const uint32_t sA = smem_base + (t & 3) * BUF_BYTES;
        const uint32_t sB = sA + 128 * SM_STRIDE;
#pragma unroll
        for (int ks = 0; ks < 2; ks++) {
            uint32_t a[4][4];
#pragma unroll
            for (int mf = 0; mf < 4; mf++) {
                const int row = wm * 64 + mf * 16 + (lane & 15);
                const uint32_t col = ks * 32 + ((lane >> 4) << 4);
                ldsm_x4(a[mf][0], a[mf][1], a[mf][2], a[mf][3],
                        sA + row * SM_STRIDE + col);
            }
            uint32_t b[4][2];
#pragma unroll
            for (int nf = 0; nf < 4; nf++) {
                const int row = wn * 32 + nf * 8 + (lane & 7);
                const uint32_t col = ks * 32 + (((lane >> 3) & 1) << 4);
                ldsm_x2(b[nf][0], b[nf][1], sB + row * SM_STRIDE + col);
            }
#pragma unroll
            for (int mf = 0; mf < 4; mf++)
#pragma unroll
                for (int nf = 0; nf < 4; nf++)
                    mma16816(acc[mf][nf], a[mf][0], a[mf][1], a[mf][2], a[mf][3],
                             b[nf][0], b[nf][1]);
        }
    }

    // ---- Epilogue 1: stores (fp32 out, bf16 c-major copy) ----
    const int r0 = lane >> 2;
    const int c0 = (lane & 3) << 1;
#pragma unroll
    for (int mf = 0; mf < 4; mf++) {
        const int bl = bm * 128 + wm * 64 + mf * 16 + r0;
#pragma unroll
        for (int nf = 0; nf < 4; nf++) {
            const int n = bn * 128 + wn * 32 + nf * 8 + c0;
            *(float2*)(out + (((size_t)bl * 8 + c) << 9) + n) =
                make_float2(acc[mf][nf][0], acc[mf][nf][1]);
            *(float2*)(out + (((size_t)(bl + 8) * 8 + c) << 9) + n) =
                make_float2(acc[mf][nf][2], acc[mf][nf][3]);
            *(__nv_bfloat162*)(g_mulbf16 + (((size_t)c * 1024 + bl) << 9) + n) =
                __halves2bfloat162(__float2bfloat16(acc[mf][nf][0]),
                                   __float2bfloat16(acc[mf][nf][1]));
            *(__nv_bfloat162*)(g_mulbf16 + (((size_t)c * 1024 + bl + 8) << 9) + n) =
                __halves2bfloat162(__float2bfloat16(acc[mf][nf][2]),
                                   __float2bfloat16(acc[mf][nf][3]));
        }
    }

    // ---- Epilogue 2: partial cnorm over this CTA's 128 n-cols ----
#pragma unroll
    for (int mf = 0; mf < 4; mf++) {
        float p1 = 0.f, p2 = 0.f;
#pragma unroll
        for (int nf = 0; nf < 4; nf++) {
            p1 += acc[mf][nf][0] * acc[mf][nf][0] + acc[mf][nf][1] * acc[mf][nf][1];
            p2 += acc[mf][nf][2] * acc[mf][nf][2] + acc[mf][nf][3] * acc[mf][nf][3];
        }
        p1 += __shfl_xor_sync(0xffffffffu, p1, 1);
        p1 += __shfl_xor_sync(0xffffffffu, p1, 2);
        p2 += __shfl_xor_sync(0xffffffffu, p2, 1);
        p2 += __shfl_xor_sync(0xffffffffu, p2, 2);
        if ((lane & 3) == 0) {
            s_part[wn][wm * 64 + mf * 16 + r0] = p1;
            s_part[wn][wm * 64 + mf * 16 + r0 + 8] = p2;
        }
    }
    __syncthreads();
    if (tid < 128) {
        const float cn = s_part[0][tid] + s_part[1][tid]
                       + s_part[2][tid] + s_part[3][tid];
        g_cnormp[bn][c * 1024 + bm * 128 + tid] = cn;
    }
}

// ---------------------------------------------------------------------------
// Dot HMMA (h-split by 2): g_dotp[hh][c][b][k64] partial over 256 h-cols.
// <<<256, 256, 73728>>>, blockIdx.x = hh*128 + bt*8 + c
// ---------------------------------------------------------------------------
#define DSTRIDE 144
#define DBUF (128 * DSTRIDE)

__global__ void __launch_bounds__(256)
dot_mma_kernel() {
    extern __shared__ __align__(16) char smem[];  // 4 * DBUF
    const uint32_t smem_base = smem_u32(smem);

    const int tid = threadIdx.x;
    const int lane = tid & 31;
    const int wid = tid >> 5;
    const int wm = wid >> 1;    // 0..3
    const int wn = wid & 1;     // 0..1
    const int c = blockIdx.x & 7;
    const int bt = (blockIdx.x >> 3) & 15;  // 0..15
    const int hh = blockIdx.x >> 7;         // 0..1

    const __nv_bfloat16* Abase =
        g_mulbf16 + (((size_t)c * 1024 + bt * 64) << 9) + hh * 256;
    const __nv_bfloat16* Bbase = g_mubf16 + ((size_t)c << 15) + hh * 256;

    const int lrow = tid >> 3;
    const int lseg = tid & 7;

    auto issue = [&](int ch) {
        const int stage = ch & 3;
        const uint32_t sA = smem_base + stage * DBUF;
        const uint32_t sB = sA + 64 * DSTRIDE;
#pragma unroll
        for (int q = 0; q < 2; q++) {
            const int row = lrow + q * 32;
            CP_ASYNC16(sA + row * DSTRIDE + lseg * 16,
                       Abase + ((size_t)row << 9) + ch * 64 + lseg * 8);
        }
#pragma unroll
        for (int q = 0; q < 2; q++) {
            const int row = lrow + q * 32;
            CP_ASYNC16(sB + row * DSTRIDE + lseg * 16,
                       Bbase + ((size_t)row << 9) + ch * 64 + lseg * 8);
        }
        CP_COMMIT();
    };

    float acc[4][4];
#pragma unroll
    for (int j = 0; j < 4; j++)
#pragma unroll
        for (int q = 0; q < 4; q++) acc[j][q] = 0.f;

    issue(0);
    issue(1);
    issue(2);

    for (int ch = 0; ch < 4; ch++) {
        if (ch <= 1)      asm volatile("cp.async.wait_group 2;" ::: "memory");
        else if (ch == 2) asm volatile("cp.async.wait_group 1;" ::: "memory");
        else              asm volatile("cp.async.wait_group 0;" ::: "memory");
        __syncthreads();
        if (ch + 3 < 4) issue(ch + 3);

        const uint32_t sA = smem_base + (ch & 3) * DBUF;
        const uint32_t sB = sA + 64 * DSTRIDE;
#pragma unroll
        for (int ks = 0; ks < 4; ks++) {
            uint32_t a[4];
            {
                const int row = wm * 16 + (lane & 15);
                const uint32_t col = ks * 32 + ((lane >> 4) << 4);
                ldsm_x4(a[0], a[1], a[2], a[3], sA + row * DSTRIDE + col);
            }
            uint32_t b[4][2];
#pragma unroll
            for (int nf = 0; nf < 4; nf++) {
                const int row = wn * 32 + nf * 8 + (lane & 7);
                const uint32_t col = ks * 32 + (((lane >> 3) & 1) << 4);
                ldsm_x2(b[nf][0], b[nf][1], sB + row * DSTRIDE + col);
            }
#pragma unroll
            for (int nf = 0; nf < 4; nf++)
                mma16816(acc[nf], a[0], a[1], a[2], a[3], b[nf][0], b[nf][1]);
        }
    }

    const int r0 = lane >> 2;
    const int c0 = (lane & 3) << 1;
    const int m = bt * 64 + wm * 16 + r0;
    float* dbase = g_dotp[hh] + (((size_t)c * 1024 + m) << 6);
#pragma unroll
    for (int nf = 0; nf < 4; nf++) {
        const int n = wn * 32 + nf * 8 + c0;
        *(float2*)(dbase + n) = make_float2(acc[nf][0], acc[nf][1]);
        *(float2*)(dbase + (8 << 6) + n) = make_float2(acc[nf][2], acc[nf][3]);
    }
}

// ---------------------------------------------------------------------------
// Epilogue: distances/k_assign from cnorm partials + dot partials.
// <<<256, 256>>>
// ---------------------------------------------------------------------------
__global__ void __launch_bounds__(256)
score_epilogue_kernel(float* __restrict__ out_ka, float* __restrict__ out_dist) {
    __shared__ float s_cnorm[32];
    const int tid = threadIdx.x;
    const int b0 = blockIdx.x;

    if (tid < 32) {
        const int bsub = tid >> 3, cc = tid & 7;
        const int b = b0 * 4 + bsub;
        s_cnorm[bsub * 8 + cc] = g_cnormp[0][cc * 1024 + b]
                               + g_cnormp[1][cc * 1024 + b]
                               + g_cnormp[2][cc * 1024 + b]
                               + g_cnormp[3][cc * 1024 + b];
    }
    __syncthreads();

    if (tid < 200) {
        const int bsub = tid / 50;
        const int k = tid % 50;
        const int b = b0 * 4 + bsub;
        float sc[8];
        float S = 0.f;
#pragma unroll
        for (int c = 0; c < 8; c++) {
            const size_t di = (((size_t)c * 1024 + b) << 6) + k;
            const float dot = g_dotp[0][di] + g_dotp[1][di];
            const float d2 = 1.f + s_cnorm[bsub * 8 + c] - 2.f * dot
                           + g_munorm[k * 8 + c];
            const float v = 1.f / d2;
            sc[c] = v;
            S += v;
        }
        const float inv1 = 1.f / (S + 1e-8f);
        float dist[8];
        float T = 0.f;
#pragma unroll
        for (int c = 0; c < 8; c++) { dist[c] = sc[c] * inv1; T += dist[c]; }
        const float inv2 = 1.f / T;
        const size_t base = ((size_t)b * 50 + k) << 3;
        float4 d01 = make_float4(dist[0], dist[1], dist[2], dist[3]);
        float4 d23 = make_float4(dist[4], dist[5], dist[6], dist[7]);
        *(float4*)(out_dist + base) = d01;
        *(float4*)(out_dist + base + 4) = d23;
        *(float4*)(out_ka + base) =
            make_float4(d01.x * inv2, d01.y * inv2, d01.z * inv2, d01.w * inv2);
        *(float4*)(out_ka + base + 4) =
            make_float4(d23.x * inv2, d23.y * inv2, d23.z * inv2, d23.w * inv2);
    }
}

// ---------------------------------------------------------------------------
extern "C" void kernel_launch(void* const* d_in, const int* in_sizes, int n_in,
                              void* d_out, int out_size) {
    const float* x        = (const float*)d_in[0];
    const float* class_mu = (const float*)d_in[1];
    const float* mask     = (const float*)d_in[2];
    const float* W        = (const float*)d_in[3];

    float* out      = (float*)d_out;
    float* out_mul  = out;                                  // 1024*8*512
    float* out_ka   = out + (size_t)1024 * 8 * 512;         // 1024*50*8
    float* out_dist = out_ka + (size_t)1024 * 50 * 8;       // 1024*50*8

    const size_t gemm_smem = 4 * BUF_BYTES;  // 81920 B
    const size_t dot_smem  = 4 * DBUF;       // 73728 B
    cudaFuncSetAttribute(mma_gemm_kernel,
                         cudaFuncAttributeMaxDynamicSharedMemorySize, (int)gemm_smem);
    cudaFuncSetAttribute(dot_mma_kernel,
                         cudaFuncAttributeMaxDynamicSharedMemorySize, (int)dot_smem);

    prep_kernel<<<4402, 256>>>(x, mask, W, class_mu);
    mma_gemm_kernel<<<dim3(4, 64), 256, gemm_smem>>>(out_mul);
    dot_mma_kernel<<<256, 256, dot_smem>>>();
    score_epilogue_kernel<<<256, 256>>>(out_ka, out_dist);
}

// round 11
// speedup vs baseline: 3.4669x; 1.0348x over previous
#include <cuda_runtime.h>
#include <cuda_bf16.h>
#include <cstdint>
#include <cstddef>

// B=1024, K=50 classes, C=8 centers, H=512
// inputs: d_in[0]=x[1024,512], d_in[1]=class_mu[50,8,512], d_in[2]=mask[8,512], d_in[3]=W[512,512]
// output: concat(mul[1024,8,512] fp32, k_assign[1024,50,8], distances[1024,50,8])
//
// mask is binary {0,1} => per-center K-compaction of the GEMM is EXACT.

// ---------------------------------------------------------------------------
// Scratch (__device__ globals — allocation-free)
// ---------------------------------------------------------------------------
__device__ int   g_kcnt[8];        // kept count per center
__device__ float g_munorm[400];
// compacted, split A: [c][b][1024]: cols [0,512)=hi(x gathered), [512,1024)=lo
__device__ __align__(16) __nv_bfloat16 g_Axc[8 * 1024 * 1024];
// compacted, split, transposed W: [c][n][1024]: hi | lo
__device__ __align__(16) __nv_bfloat16 g_Wc[8 * 512 * 1024];
// bf16 copy of mul, c-major: [c][b][h]
__device__ __align__(16) __nv_bfloat16 g_mulbf16[8 * 1024 * 512];
// bf16 padded class_mu, c-major: [c][k64][h], zeros for k>=50
__device__ __align__(16) __nv_bfloat16 g_mubf16[8 * 64 * 512];
// dot partials: [half][c][b][k64] fp32
__device__ __align__(16) float g_dotp[2][8 * 1024 * 64];
// per-bn partial ||mul[b,c]||^2: [bn][c*1024+b]
__device__ float g_cnormp[4][8 * 1024];

// ---------------------------------------------------------------------------
// PTX helpers (baseline sm_103 target — no 'a'-suffix features)
// ---------------------------------------------------------------------------
__device__ __forceinline__ uint32_t smem_u32(const void* p) {
    uint32_t a;
    asm("{ .reg .u64 t; cvta.to.shared.u64 t, %1; cvt.u32.u64 %0, t; }"
        : "=r"(a) : "l"(p));
    return a;
}

__device__ __forceinline__ void ldsm_x4(uint32_t& r0, uint32_t& r1, uint32_t& r2,
                                        uint32_t& r3, uint32_t addr) {
    asm volatile("ldmatrix.sync.aligned.m8n8.x4.shared.b16 {%0,%1,%2,%3}, [%4];"
                 : "=r"(r0), "=r"(r1), "=r"(r2), "=r"(r3) : "r"(addr));
}

__device__ __forceinline__ void ldsm_x2(uint32_t& r0, uint32_t& r1, uint32_t addr) {
    asm volatile("ldmatrix.sync.aligned.m8n8.x2.shared.b16 {%0,%1}, [%2];"
                 : "=r"(r0), "=r"(r1) : "r"(addr));
}

__device__ __forceinline__ void mma16816(float* c, uint32_t a0, uint32_t a1,
                                         uint32_t a2, uint32_t a3,
                                         uint32_t b0, uint32_t b1) {
    asm volatile(
        "mma.sync.aligned.m16n8k16.row.col.f32.bf16.bf16.f32 "
        "{%0,%1,%2,%3}, {%4,%5,%6,%7}, {%8,%9}, {%0,%1,%2,%3};"
        : "+f"(c[0]), "+f"(c[1]), "+f"(c[2]), "+f"(c[3])
        : "r"(a0), "r"(a1), "r"(a2), "r"(a3), "r"(b0), "r"(b1));
}

#define CP_ASYNC16(dst, src) \
    asm volatile("cp.async.cg.shared.global [%0], [%1], 16;" \
                 :: "r"(dst), "l"(src) : "memory")
#define CP_COMMIT() asm volatile("cp.async.commit_group;" ::: "memory")

// ---------------------------------------------------------------------------
// In-block mask compaction: 256 threads, warp w owns elements [w*64, w*64+64).
// ---------------------------------------------------------------------------
__device__ __forceinline__ int compact_mask(const float* __restrict__ mask_row,
                                            int tid, int* s_kidx, int* s_wcnt) {
    const int lane = tid & 31;
    const int warp = tid >> 5;  // 0..7
    const int e0 = warp * 64 + lane;
    const int e1 = e0 + 32;
    const int p0 = (mask_row[e0] != 0.f) ? 1 : 0;
    const int p1 = (mask_row[e1] != 0.f) ? 1 : 0;
    const unsigned b0 = __ballot_sync(0xffffffffu, p0);
    const unsigned b1 = __ballot_sync(0xffffffffu, p1);
    const int c0 = __popc(b0);
    if (lane == 0) s_wcnt[warp] = c0 + __popc(b1);
    __syncthreads();
    int base = 0, total = 0;
#pragma unroll
    for (int w = 0; w < 8; w++) {
        if (w < warp) base += s_wcnt[w];
        total += s_wcnt[w];
    }
    if (p0) s_kidx[base + __popc(b0 & ((1u << lane) - 1u))] = e0;
    if (p1) s_kidx[base + c0 + __popc(b1 & ((1u << lane) - 1u))] = e1;
    for (int j = total + tid; j < 512; j += 256) s_kidx[j] = 0;
    __syncthreads();
    return total;
}

// ---------------------------------------------------------------------------
// Prep: gather+split A (4 rows/blk) | gather+transpose+split W | munorm | mubf16
// grid = 2048 + 2048 + 50 + 256 = 4402, 256 threads
// ---------------------------------------------------------------------------
__global__ void prep_kernel(const float* __restrict__ x,
                            const float* __restrict__ mask,
                            const float* __restrict__ W,
                            const float* __restrict__ class_mu) {
    __shared__ int s_kidx[512];
    __shared__ int s_wcnt[8];
    __shared__ float s_x[4][512];
    __shared__ float tile[32][33];
    const int tid = threadIdx.x;
    const int blk = blockIdx.x;

    if (blk < 2048) {
        // ---- gather + split A: 4 b-rows per block ----
        const int c = blk >> 8;
        const int bq = blk & 255;
        for (int i = tid; i < 4 * 512; i += 256)
            s_x[i >> 9][i & 511] = x[(size_t)(bq * 4 + (i >> 9)) * 512 + (i & 511)];
        const int total = compact_mask(mask + c * 512, tid, s_kidx, s_wcnt);
        if (bq == 0 && tid == 0) g_kcnt[c] = total;
        const int nch32 = ((total + 31) >> 5) << 5;
        const int j2 = tid * 2;
        if (j2 < nch32) {
            const int i0 = s_kidx[j2];
            const int i1 = s_kidx[j2 + 1];
            const bool v0ok = j2 < total, v1ok = (j2 + 1) < total;
#pragma unroll
            for (int r = 0; r < 4; r++) {
                const float v0 = v0ok ? s_x[r][i0] : 0.f;
                const float v1 = v1ok ? s_x[r][i1] : 0.f;
                const __nv_bfloat16 h0 = __float2bfloat16(v0);
                const __nv_bfloat16 h1 = __float2bfloat16(v1);
                const __nv_bfloat16 l0 = __float2bfloat16(v0 - __bfloat162float(h0));
                const __nv_bfloat16 l1 = __float2bfloat16(v1 - __bfloat162float(h1));
                __nv_bfloat16* base =
                    g_Axc + (((size_t)c * 1024 + bq * 4 + r) << 10);
                *(__nv_bfloat162*)(base + j2)       = __halves2bfloat162(h0, h1);
                *(__nv_bfloat162*)(base + 512 + j2) = __halves2bfloat162(l0, l1);
            }
        }
    } else if (blk < 4096) {
        // ---- gather + transpose + split W ----
        const int t = blk - 2048;
        const int c = t >> 8;
        const int jt = (t >> 4) & 15, nt = t & 15;
        const int total = compact_mask(mask + c * 512, tid, s_kidx, s_wcnt);
        const int nch32 = ((total + 31) >> 5) << 5;
        if (jt * 32 >= nch32) return;
        const int tx = tid & 31, ty = tid >> 5;
#pragma unroll
        for (int i = 0; i < 32; i += 8) {
            const int j = jt * 32 + ty + i;
            tile[ty + i][tx] = (j < total)
                ? W[(size_t)s_kidx[j] * 512 + nt * 32 + tx] : 0.f;
        }
        __syncthreads();
#pragma unroll
        for (int i = 0; i < 32; i += 8) {
            const int n = nt * 32 + ty + i;
            const int j = jt * 32 + tx;
            const float v = tile[tx][ty + i];
            const __nv_bfloat16 hi = __float2bfloat16(v);
            const __nv_bfloat16 lo = __float2bfloat16(v - __bfloat162float(hi));
            __nv_bfloat16* base = g_Wc + (((size_t)c * 512 + n) << 10);
            base[j] = hi;
            base[512 + j] = lo;
        }
    } else if (blk < 4096 + 50) {
        // ---- munorm ----
        const int warp = tid >> 5;
        const int lane = tid & 31;
        const int r = (blk - 4096) * 8 + warp;
        const float4* row = (const float4*)(class_mu + (size_t)r * 512);
        float s = 0.f;
#pragma unroll
        for (int j = lane; j < 128; j += 32) {
            float4 v = row[j];
            s += v.x * v.x + v.y * v.y + v.z * v.z + v.w * v.w;
        }
#pragma unroll
        for (int o = 16; o; o >>= 1) s += __shfl_down_sync(0xffffffffu, s, o);
        if (lane == 0) g_munorm[r] = s;
    } else {
        // ---- class_mu -> g_mubf16[c][k64][h], zero padded ----
        const int t = blk - 4146;
        const int idx4 = t * 256 + tid;
        const int row = idx4 >> 7;
        const int h = (idx4 & 127) << 2;
        const int c = row >> 6, k = row & 63;
        float4 v = make_float4(0.f, 0.f, 0.f, 0.f);
        if (k < 50) v = *(const float4*)(class_mu + (((size_t)k * 8 + c) << 9) + h);
        __nv_bfloat162* dst = (__nv_bfloat162*)(g_mubf16 + (size_t)row * 512 + h);
        dst[0] = __halves2bfloat162(__float2bfloat16(v.x), __float2bfloat16(v.y));
        dst[1] = __halves2bfloat162(__float2bfloat16(v.z), __float2bfloat16(v.w));
    }
}

// ---------------------------------------------------------------------------
// K-compacted HMMA GEMM, per-center: mul[b,c,:] = Axc[c] @ Wc[c]^T
// <<<dim3(4, 64), 256, 81920>>>, blockIdx.y = c*8 + bm
// ---------------------------------------------------------------------------
#define SM_STRIDE 80
#define BUF_BYTES 20480

__global__ void __launch_bounds__(256, 2)
mma_gemm_kernel(float* __restrict__ out) {
    extern __shared__ __align__(16) char smem[];  // 4 * BUF_BYTES
    __shared__ float s_part[4][128];
    const uint32_t smem_base = smem_u32(smem);

    const int tid = threadIdx.x;
    const int lane = tid & 31;
    const int wid = tid >> 5;
    const int wm = wid >> 2;
    const int wn = wid & 3;
    const int bn = blockIdx.x;
    const int c  = blockIdx.y >> 3;
    const int bm = blockIdx.y & 7;

    const int kcnt = g_kcnt[c];
    const int nch = (kcnt + 31) >> 5;
    const int T = 3 * nch;

    const __nv_bfloat16* Abase = g_Axc + (((size_t)c * 1024 + bm * 128) << 10);
    const __nv_bfloat16* Bbase = g_Wc  + (((size_t)c * 512  + bn * 128) << 10);

    const int lrow = tid >> 2;
    const int lseg = tid & 3;

    auto issue = [&](int t) {
        const int stage = t & 3;
        const int p = (t >= 2 * nch) ? 2 : ((t >= nch) ? 1 : 0);
        const int sub = t - p * nch;
        const int acol = ((p == 2) ? 512 : 0) + sub * 32;  // A: hi,hi,lo
        const int bcol = ((p == 1) ? 512 : 0) + sub * 32;  // B: hi,lo,hi
        const uint32_t sA = smem_base + stage * BUF_BYTES;
        const uint32_t sB = sA + 128 * SM_STRIDE;
#pragma unroll
        for (int q = 0; q < 2; q++) {
            const int row = lrow + q * 64;
            CP_ASYNC16(sA + row * SM_STRIDE + lseg * 16,
                       Abase + ((size_t)row << 10) + acol + lseg * 8);
        }
#pragma unroll
        for (int q = 0; q < 2; q++) {
            const int row = lrow + q * 64;
            CP_ASYNC16(sB + row * SM_STRIDE + lseg * 16,
                       Bbase + ((size_t)row << 10) + bcol + lseg * 8);
        }
        CP_COMMIT();
    };

    float acc[4][4][4];
#pragma unroll
    for (int i = 0; i < 4; i++)
#pragma unroll
        for (int j = 0; j < 4; j++)
#pragma unroll
            for (int q = 0; q < 4; q++) acc[i][j][q] = 0.f;

    issue(0);
    issue(1);
    issue(2);

    for (int t = 0; t < T; t++) {
        if (t <= T - 3)      asm volatile("cp.async.wait_group 2;" ::: "memory");
        else if (t == T - 2) asm volatile("cp.async.wait_group 1;" ::: "memory");
        else                 asm volatile("cp.async.wait_group 0;" ::: "memory");
        __syncthreads();
        if (t + 3 < T) issue(t + 3);

        const uint32_t sA = smem_base + (t & 3) * BUF_BYTES;
        const uint32_t sB = sA + 128 * SM_STRIDE;
#pragma unroll
        for (int ks = 0; ks < 2; ks++) {
            uint32_t a[4][4];
#pragma unroll
            for (int mf = 0; mf < 4; mf++) {
                const int row = wm * 64 + mf * 16 + (lane & 15);
                const uint32_t col = ks * 32 + ((lane >> 4) << 4);
                ldsm_x4(a[mf][0], a[mf][1], a[mf][2], a[mf][3],
                        sA + row * SM_STRIDE + col);
            }
            uint32_t b[4][2];
#pragma unroll
            for (int nf = 0; nf < 4; nf++) {
                const int row = wn * 32 + nf * 8 + (lane & 7);
                const uint32_t col = ks * 32 + (((lane >> 3) & 1) << 4);
                ldsm_x2(b[nf][0], b[nf][1], sB + row * SM_STRIDE + col);
            }
#pragma unroll
            for (int mf = 0; mf < 4; mf++)
#pragma unroll
                for (int nf = 0; nf < 4; nf++)
                    mma16816(acc[mf][nf], a[mf][0], a[mf][1], a[mf][2], a[mf][3],
                             b[nf][0], b[nf][1]);
        }
    }

    // ---- Epilogue 1: stores (fp32 out, bf16 c-major copy) ----
    const int r0 = lane >> 2;
    const int c0 = (lane & 3) << 1;
#pragma unroll
    for (int mf = 0; mf < 4; mf++) {
        const int bl = bm * 128 + wm * 64 + mf * 16 + r0;
#pragma unroll
        for (int nf = 0; nf < 4; nf++) {
            const int n = bn * 128 + wn * 32 + nf * 8 + c0;
            *(float2*)(out + (((size_t)bl * 8 + c) << 9) + n) =
                make_float2(acc[mf][nf][0], acc[mf][nf][1]);
            *(float2*)(out + (((size_t)(bl + 8) * 8 + c) << 9) + n) =
                make_float2(acc[mf][nf][2], acc[mf][nf][3]);
            *(__nv_bfloat162*)(g_mulbf16 + (((size_t)c * 1024 + bl) << 9) + n) =
                __halves2bfloat162(__float2bfloat16(acc[mf][nf][0]),
                                   __float2bfloat16(acc[mf][nf][1]));
            *(__nv_bfloat162*)(g_mulbf16 + (((size_t)c * 1024 + bl + 8) << 9) + n) =
                __halves2bfloat162(__float2bfloat16(acc[mf][nf][2]),
                                   __float2bfloat16(acc[mf][nf][3]));
        }
    }

    // ---- Epilogue 2: partial cnorm over this CTA's 128 n-cols ----
#pragma unroll
    for (int mf = 0; mf < 4; mf++) {
        float p1 = 0.f, p2 = 0.f;
#pragma unroll
        for (int nf = 0; nf < 4; nf++) {
            p1 += acc[mf][nf][0] * acc[mf][nf][0] + acc[mf][nf][1] * acc[mf][nf][1];
            p2 += acc[mf][nf][2] * acc[mf][nf][2] + acc[mf][nf][3] * acc[mf][nf][3];
        }
        p1 += __shfl_xor_sync(0xffffffffu, p1, 1);
        p1 += __shfl_xor_sync(0xffffffffu, p1, 2);
        p2 += __shfl_xor_sync(0xffffffffu, p2, 1);
        p2 += __shfl_xor_sync(0xffffffffu, p2, 2);
        if ((lane & 3) == 0) {
            s_part[wn][wm * 64 + mf * 16 + r0] = p1;
            s_part[wn][wm * 64 + mf * 16 + r0 + 8] = p2;
        }
    }
    __syncthreads();
    if (tid < 128) {
        const float cn = s_part[0][tid] + s_part[1][tid]
                       + s_part[2][tid] + s_part[3][tid];
        g_cnormp[bn][c * 1024 + bm * 128 + tid] = cn;
    }
}

// ---------------------------------------------------------------------------
// Dot HMMA (h-split by 2): g_dotp[hh][c][b][k64] partial over 256 h-cols.
// <<<256, 256, 73728>>>, blockIdx.x = hh*128 + bt*8 + c
// ---------------------------------------------------------------------------
#define DSTRIDE 144
#define DBUF (128 * DSTRIDE)

__global__ void __launch_bounds__(256)
dot_mma_kernel() {
    extern __shared__ __align__(16) char smem[];  // 4 * DBUF
    const uint32_t smem_base = smem_u32(smem);

    const int tid = threadIdx.x;
    const int lane = tid & 31;
    const int wid = tid >> 5;
    const int wm = wid >> 1;
    const int wn = wid & 1;
    const int c = blockIdx.x & 7;
    const int bt = (blockIdx.x >> 3) & 15;
    const int hh = blockIdx.x >> 7;

    const __nv_bfloat16* Abase =
        g_mulbf16 + (((size_t)c * 1024 + bt * 64) << 9) + hh * 256;
    const __nv_bfloat16* Bbase = g_mubf16 + ((size_t)c << 15) + hh * 256;

    const int lrow = tid >> 3;
    const int lseg = tid & 7;

    auto issue = [&](int ch) {
        const int stage = ch & 3;
        const uint32_t sA = smem_base + stage * DBUF;
        const uint32_t sB = sA + 64 * DSTRIDE;
#pragma unroll
        for (int q = 0; q < 2; q++) {
            const int row = lrow + q * 32;
            CP_ASYNC16(sA + row * DSTRIDE + lseg * 16,
                       Abase + ((size_t)row << 9) + ch * 64 + lseg * 8);
        }
#pragma unroll
        for (int q = 0; q < 2; q++) {
            const int row = lrow + q * 32;
            CP_ASYNC16(sB + row * DSTRIDE + lseg * 16,
                       Bbase + ((size_t)row << 9) + ch * 64 + lseg * 8);
        }
        CP_COMMIT();
    };

    float acc[4][4];
#pragma unroll
    for (int j = 0; j < 4; j++)
#pragma unroll
        for (int q = 0; q < 4; q++) acc[j][q] = 0.f;

    issue(0);
    issue(1);
    issue(2);

    for (int ch = 0; ch < 4; ch++) {
        if (ch <= 1)      asm volatile("cp.async.wait_group 2;" ::: "memory");
        else if (ch == 2) asm volatile("cp.async.wait_group 1;" ::: "memory");
        else              asm volatile("cp.async.wait_group 0;" ::: "memory");
        __syncthreads();
        if (ch + 3 < 4) issue(ch + 3);

        const uint32_t sA = smem_base + (ch & 3) * DBUF;
        const uint32_t sB = sA + 64 * DSTRIDE;
#pragma unroll
        for (int ks = 0; ks < 4; ks++) {
            uint32_t a[4];
            {
                const int row = wm * 16 + (lane & 15);
                const uint32_t col = ks * 32 + ((lane >> 4) << 4);
                ldsm_x4(a[0], a[1], a[2], a[3], sA + row * DSTRIDE + col);
            }
            uint32_t b[4][2];
#pragma unroll
            for (int nf = 0; nf < 4; nf++) {
                const int row = wn * 32 + nf * 8 + (lane & 7);
                const uint32_t col = ks * 32 + (((lane >> 3) & 1) << 4);
                ldsm_x2(b[nf][0], b[nf][1], sB + row * DSTRIDE + col);
            }
#pragma unroll
            for (int nf = 0; nf < 4; nf++)
                mma16816(acc[nf], a[0], a[1], a[2], a[3], b[nf][0], b[nf][1]);
        }
    }

    const int r0 = lane >> 2;
    const int c0 = (lane & 3) << 1;
    const int m = bt * 64 + wm * 16 + r0;
    float* dbase = g_dotp[hh] + (((size_t)c * 1024 + m) << 6);
#pragma unroll
    for (int nf = 0; nf < 4; nf++) {
        const int n = wn * 32 + nf * 8 + c0;
        *(float2*)(dbase + n) = make_float2(acc[nf][0], acc[nf][1]);
        *(float2*)(dbase + (8 << 6) + n) = make_float2(acc[nf][2], acc[nf][3]);
    }
}

// ---------------------------------------------------------------------------
// Epilogue: coalesced smem staging of dots, then distances/k_assign.
// One block = 8 b-rows. <<<128, 256>>>
// ---------------------------------------------------------------------------
__global__ void __launch_bounds__(256)
score_epilogue_kernel(float* __restrict__ out_ka, float* __restrict__ out_dist) {
    __shared__ float s_dot[8][8][64];   // [c][bsub][k]  16 KB
    __shared__ float s_cnorm[64];       // [bsub*8+c]
    const int tid = threadIdx.x;
    const int b0 = blockIdx.x;          // b rows b0*8 .. b0*8+7

    // Bulk-load dots: 64 rows (c,bsub) x 64 floats, both halves summed.
    // 1024 float4 positions, 4 per thread, fully coalesced per row.
#pragma unroll
    for (int it = 0; it < 4; it++) {
        const int pos = tid + it * 256;          // 0..1023
        const int r = pos >> 4;                  // 0..63 = c*8+bsub
        const int seg = pos & 15;                // float4 index within row
        const int c = r >> 3, bsub = r & 7;
        const size_t gi = ((((size_t)c * 1024 + b0 * 8 + bsub) << 6) + seg * 4);
        const float4 u = *(const float4*)(g_dotp[0] + gi);
        const float4 v = *(const float4*)(g_dotp[1] + gi);
        *(float4*)&s_dot[c][bsub][seg * 4] =
            make_float4(u.x + v.x, u.y + v.y, u.z + v.z, u.w + v.w);
    }
    if (tid < 64) {
        const int bsub = tid >> 3, cc = tid & 7;
        const int b = b0 * 8 + bsub;
        s_cnorm[tid] = g_cnormp[0][cc * 1024 + b] + g_cnormp[1][cc * 1024 + b]
                     + g_cnormp[2][cc * 1024 + b] + g_cnormp[3][cc * 1024 + b];
    }
    __syncthreads();

    for (int p = tid; p < 400; p += 256) {
        const int bsub = p / 50;
        const int k = p % 50;
        const int b = b0 * 8 + bsub;
        float sc[8];
        float S = 0.f;
#pragma unroll
        for (int c = 0; c < 8; c++) {
            const float d2 = 1.f + s_cnorm[bsub * 8 + c] - 2.f * s_dot[c][bsub][k]
                           + g_munorm[k * 8 + c];
            const float v = 1.f / d2;
            sc[c] = v;
            S += v;
        }
        const float inv1 = 1.f / (S + 1e-8f);
        float dist[8];
        float T = 0.f;
#pragma unroll
        for (int c = 0; c < 8; c++) { dist[c] = sc[c] * inv1; T += dist[c]; }
        const float inv2 = 1.f / T;
        const size_t base = ((size_t)b * 50 + k) << 3;
        float4 d01 = make_float4(dist[0], dist[1], dist[2], dist[3]);
        float4 d23 = make_float4(dist[4], dist[5], dist[6], dist[7]);
        *(float4*)(out_dist + base) = d01;
        *(float4*)(out_dist + base + 4) = d23;
        *(float4*)(out_ka + base) =
            make_float4(d01.x * inv2, d01.y * inv2, d01.z * inv2, d01.w * inv2);
        *(float4*)(out_ka + base + 4) =
            make_float4(d23.x * inv2, d23.y * inv2, d23.z * inv2, d23.w * inv2);
    }
}

// ---------------------------------------------------------------------------
extern "C" void kernel_launch(void* const* d_in, const int* in_sizes, int n_in,
                              void* d_out, int out_size) {
    const float* x        = (const float*)d_in[0];
    const float* class_mu = (const float*)d_in[1];
    const float* mask     = (const float*)d_in[2];
    const float* W        = (const float*)d_in[3];

    float* out      = (float*)d_out;
    float* out_mul  = out;                                  // 1024*8*512
    float* out_ka   = out + (size_t)1024 * 8 * 512;         // 1024*50*8
    float* out_dist = out_ka + (size_t)1024 * 50 * 8;       // 1024*50*8

    const size_t gemm_smem = 4 * BUF_BYTES;  // 81920 B
    const size_t dot_smem  = 4 * DBUF;       // 73728 B
    cudaFuncSetAttribute(mma_gemm_kernel,
                         cudaFuncAttributeMaxDynamicSharedMemorySize, (int)gemm_smem);
    cudaFuncSetAttribute(dot_mma_kernel,
                         cudaFuncAttributeMaxDynamicSharedMemorySize, (int)dot_smem);

    prep_kernel<<<4402, 256>>>(x, mask, W, class_mu);
    mma_gemm_kernel<<<dim3(4, 64), 256, gemm_smem>>>(out_mul);
    dot_mma_kernel<<<256, 256, dot_smem>>>();
    score_epilogue_kernel<<<128, 256>>>(out_ka, out_dist);
}